// round 10
// baseline (speedup 1.0000x reference)
#include <cuda_runtime.h>
#include <cuda_bf16.h>
#include <math.h>
#include <math_constants.h>
#include <stdint.h>

#define NN 20000
#define EE 160000
#define DD 128
#define NFUSE 1664   // 512(q)+512(k)+512(v)+128(skip)

// ---------------- scratch (static device globals; no allocation) ----------------
__device__ float g_qkvs[NN * NFUSE];   // fused q|k|v|skip, row stride 1664
__device__ float g_den[NN * 4];
__device__ float g_agg[NN * 512];      // UNNORMALIZED sum of ex*v
__device__ float g_x1[NN * DD];
__device__ float g_tout[NN * DD];
__device__ float g_x2[NN * DD];
__device__ float g_ffn[NN * DD];
__device__ float g_bias_f[NFUSE];

// bf16 hi/lo operand buffers
__device__ __nv_bfloat16 g_xh[NN * DD],  g_xl[NN * DD];
__device__ __nv_bfloat16 g_teh[NN * DD], g_tel[NN * DD];
__device__ __nv_bfloat16 g_tvh[NN * DD], g_tvl[NN * DD];
__device__ __nv_bfloat16 g_x2h[NN * DD], g_x2l[NN * DD];
__device__ __nv_bfloat16 g_hh[NN * 512], g_hl[NN * 512];
__device__ __nv_bfloat16 g_wfh[NFUSE * 128], g_wfl[NFUSE * 128];
__device__ __nv_bfloat16 g_mvh[128 * 128], g_mvl[128 * 128];
__device__ __nv_bfloat16 g_moh[128 * 128], g_mol[128 * 128];
__device__ __nv_bfloat16 g_w1h[512 * 128], g_w1l[512 * 128];
__device__ __nv_bfloat16 g_w2h[128 * 512], g_w2l[128 * 512];

// ---------------- helpers ----------------
__device__ __forceinline__ void split2(float x, float y,
                                       __nv_bfloat162& h, __nv_bfloat162& l) {
    __nv_bfloat16 hx = __float2bfloat16(x);
    __nv_bfloat16 hy = __float2bfloat16(y);
    __nv_bfloat16 lx = __float2bfloat16(x - __bfloat162float(hx));
    __nv_bfloat16 ly = __float2bfloat16(y - __bfloat162float(hy));
    h = __halves2bfloat162(hx, hy);
    l = __halves2bfloat162(lx, ly);
}

__device__ __forceinline__ void mma_bf16(float* c, const uint32_t* a, const uint32_t* b) {
    asm volatile(
        "mma.sync.aligned.m16n8k16.row.col.f32.bf16.bf16.f32 "
        "{%0,%1,%2,%3}, {%4,%5,%6,%7}, {%8,%9}, {%0,%1,%2,%3};"
        : "+f"(c[0]), "+f"(c[1]), "+f"(c[2]), "+f"(c[3])
        : "r"(a[0]), "r"(a[1]), "r"(a[2]), "r"(a[3]), "r"(b[0]), "r"(b[1]));
}

__device__ __forceinline__ void ldsm_x4(uint32_t& r0, uint32_t& r1, uint32_t& r2,
                                        uint32_t& r3, uint32_t addr) {
    asm volatile("ldmatrix.sync.aligned.m8n8.x4.shared.b16 {%0,%1,%2,%3}, [%4];"
                 : "=r"(r0), "=r"(r1), "=r"(r2), "=r"(r3) : "r"(addr));
}

__device__ __forceinline__ void cp16(uint32_t dst, const void* src) {
    asm volatile("cp.async.cg.shared.global [%0], [%1], 16;" :: "r"(dst), "l"(src));
}

// ---------------- init: den=0, agg=0 ----------------
__global__ void init_kernel() {
    int idx = blockIdx.x * blockDim.x + threadIdx.x;
    if (idx < NN * 128) reinterpret_cast<float4*>(g_agg)[idx] =
        make_float4(0.f, 0.f, 0.f, 0.f);
    if (idx < NN * 4) g_den[idx] = 0.f;
}

__global__ void bias_concat(const float* a, const float* b,
                            const float* c, const float* d) {
    int i = blockIdx.x * blockDim.x + threadIdx.x;
    if (i < 512) g_bias_f[i] = a[i];
    else if (i < 1024) g_bias_f[i] = b[i - 512];
    else if (i < 1536) g_bias_f[i] = c[i - 1024];
    else if (i < NFUSE) g_bias_f[i] = d[i - 1536];
}

// ---------------- batched fp32 -> bf16 hi/lo conversion ----------------
struct CJ { const float* s; __nv_bfloat16* h; __nv_bfloat16* l; int n4; };
struct CJs { CJ j[10]; };

__global__ void conv_batch(CJs jobs) {
    CJ job = jobs.j[blockIdx.y];
    int stride = gridDim.x * blockDim.x;
    for (int i = blockIdx.x * blockDim.x + threadIdx.x; i < job.n4; i += stride) {
        float4 v = reinterpret_cast<const float4*>(job.s)[i];
        __nv_bfloat162 h01, l01, h23, l23;
        split2(v.x, v.y, h01, l01);
        split2(v.z, v.w, h23, l23);
        reinterpret_cast<__nv_bfloat162*>(job.h)[2 * i]     = h01;
        reinterpret_cast<__nv_bfloat162*>(job.h)[2 * i + 1] = h23;
        reinterpret_cast<__nv_bfloat162*>(job.l)[2 * i]     = l01;
        reinterpret_cast<__nv_bfloat162*>(job.l)[2 * i + 1] = l23;
    }
}

// ---------------- bf16x3 mma.sync GEMM ----------------
// C[M,Nc] = A[M,K] @ W[Nc,K]^T + bias. Block tile 128(M) x 128(N), 8 warps
// (4m x 2n), warp tile 32x64. K in 64-wide chunks, 2-stage cp.async double
// buffer (prefetch chunk c+1 under compute of chunk c). 1 CTA/SM (147KB smem).
#define LDK2 72                       // 64 + 8 pad; row stride 144B (conflict-free ldsm)
#define CH_A_H 0
#define CH_A_L (128 * LDK2 * 2)       // 18432
#define CH_W_H (2 * 128 * LDK2 * 2)   // 36864
#define CH_W_L (3 * 128 * LDK2 * 2)   // 55296
#define STG    (4 * 128 * LDK2 * 2)   // 73728 per stage
#define SM_TOT (2 * STG)              // 147456 bytes

template<bool BF16OUT, bool RELU>
__global__ __launch_bounds__(256) void gemm_tc(
    const __nv_bfloat16* __restrict__ Ah, const __nv_bfloat16* __restrict__ Al,
    const __nv_bfloat16* __restrict__ Wh, const __nv_bfloat16* __restrict__ Wl,
    const float* __restrict__ bias,
    float* __restrict__ Cf, __nv_bfloat16* __restrict__ Ch,
    __nv_bfloat16* __restrict__ Cl,
    int M, int Nc, int K)
{
    extern __shared__ char smem[];
    const uint32_t smb = (uint32_t)__cvta_generic_to_shared(smem);

    const int tid  = threadIdx.x;
    const int lane = tid & 31;
    const int w    = tid >> 5;
    const int wm   = w & 3;       // 4 m-warps (32 rows each)
    const int wn   = w >> 2;      // 2 n-warps (64 cols each)
    const int bm   = blockIdx.y * 128;
    const int bn   = blockIdx.x * 128;

    const int lrow = lane & 7;
    const int quad = lane >> 3;
    const int a_roff = lrow + ((quad & 1) << 3);
    const int a_coff = (quad >> 1) << 3;
    const int b_roff = lrow + ((quad >> 1) << 3);
    const int b_coff = (quad & 1) << 3;

    float acc[2][8][4];
#pragma unroll
    for (int i = 0; i < 2; i++)
#pragma unroll
        for (int j = 0; j < 8; j++)
#pragma unroll
            for (int t = 0; t < 4; t++) acc[i][j][t] = 0.f;

    // staging: i = tid + it*256; row = i>>3 (0..127), c16 = i&7 (8 elems each)
    const int s_row = tid >> 3;
    const int s_c16 = tid & 7;

    auto stage_fn = [&](int s, int k0) {
        uint32_t base = smb + s * STG;
#pragma unroll
        for (int it = 0; it < 4; it++) {
            int row = s_row + it * 32;
            uint32_t d = base + (row * LDK2 + s_c16 * 8) * 2;
            int ga = bm + row; if (ga >= M) ga = M - 1;
            size_t aoff = (size_t)ga * K + k0 + s_c16 * 8;
            cp16(d + CH_A_H, Ah + aoff);
            cp16(d + CH_A_L, Al + aoff);
            size_t woff = (size_t)(bn + row) * K + k0 + s_c16 * 8;
            cp16(d + CH_W_H, Wh + woff);
            cp16(d + CH_W_L, Wl + woff);
        }
        asm volatile("cp.async.commit_group;");
    };

    const int nCh = K >> 6;
    stage_fn(0, 0);

    for (int c = 0; c < nCh; c++) {
        if (c + 1 < nCh) {
            stage_fn((c + 1) & 1, (c + 1) << 6);
            asm volatile("cp.async.wait_group 1;");
        } else {
            asm volatile("cp.async.wait_group 0;");
        }
        __syncthreads();

        uint32_t base = smb + (c & 1) * STG;
#pragma unroll
        for (int ks = 0; ks < 64; ks += 16) {
            uint32_t ahf[2][4], alf[2][4], bhf[8][2], blf[8][2];
#pragma unroll
            for (int i = 0; i < 2; i++) {
                uint32_t off = (uint32_t)(((wm * 32 + i * 16 + a_roff) * LDK2
                                           + ks + a_coff) * 2);
                ldsm_x4(ahf[i][0], ahf[i][1], ahf[i][2], ahf[i][3],
                        base + CH_A_H + off);
                ldsm_x4(alf[i][0], alf[i][1], alf[i][2], alf[i][3],
                        base + CH_A_L + off);
            }
#pragma unroll
            for (int jp = 0; jp < 4; jp++) {
                uint32_t off = (uint32_t)(((wn * 64 + jp * 16 + b_roff) * LDK2
                                           + ks + b_coff) * 2);
                ldsm_x4(bhf[2 * jp][0], bhf[2 * jp][1],
                        bhf[2 * jp + 1][0], bhf[2 * jp + 1][1],
                        base + CH_W_H + off);
                ldsm_x4(blf[2 * jp][0], blf[2 * jp][1],
                        blf[2 * jp + 1][0], blf[2 * jp + 1][1],
                        base + CH_W_L + off);
            }
#pragma unroll
            for (int i = 0; i < 2; i++)
#pragma unroll
                for (int j = 0; j < 8; j++) {
                    mma_bf16(acc[i][j], ahf[i], bhf[j]);
                    mma_bf16(acc[i][j], ahf[i], blf[j]);
                    mma_bf16(acc[i][j], alf[i], bhf[j]);
                }
        }
        __syncthreads();   // compute done before next prefetch overwrites buffer
    }

    // ---- epilogue ----
    const int qr = lane >> 2;
    const int kq = (lane & 3) * 2;
#pragma unroll
    for (int i = 0; i < 2; i++) {
        int r0 = bm + wm * 32 + i * 16 + qr;
#pragma unroll
        for (int j = 0; j < 8; j++) {
            int cix = bn + wn * 64 + j * 8 + kq;
            float b0 = bias[cix], b1 = bias[cix + 1];
            float v0 = acc[i][j][0] + b0, v1 = acc[i][j][1] + b1;
            float v2 = acc[i][j][2] + b0, v3 = acc[i][j][3] + b1;
            if (RELU) {
                v0 = fmaxf(v0, 0.f); v1 = fmaxf(v1, 0.f);
                v2 = fmaxf(v2, 0.f); v3 = fmaxf(v3, 0.f);
            }
            if (!BF16OUT) {
                if (r0 < M)
                    *reinterpret_cast<float2*>(Cf + (size_t)r0 * Nc + cix) =
                        make_float2(v0, v1);
                if (r0 + 8 < M)
                    *reinterpret_cast<float2*>(Cf + (size_t)(r0 + 8) * Nc + cix) =
                        make_float2(v2, v3);
            } else {
                __nv_bfloat162 hh2, ll2;
                if (r0 < M) {
                    split2(v0, v1, hh2, ll2);
                    *reinterpret_cast<__nv_bfloat162*>(Ch + (size_t)r0 * Nc + cix) = hh2;
                    *reinterpret_cast<__nv_bfloat162*>(Cl + (size_t)r0 * Nc + cix) = ll2;
                }
                if (r0 + 8 < M) {
                    split2(v2, v3, hh2, ll2);
                    *reinterpret_cast<__nv_bfloat162*>(Ch + (size_t)(r0 + 8) * Nc + cix) = hh2;
                    *reinterpret_cast<__nv_bfloat162*>(Cl + (size_t)(r0 + 8) * Nc + cix) = ll2;
                }
            }
        }
    }
}

// ---------------- fused edge phase (single pass) ----------------
// Softmax is shift-invariant and alpha = <q,k>/sqrt(128) is O(0.01) here, so no
// max-subtraction is needed. Scatter UNNORMALIZED ex*v and den; ln1 divides.
__global__ void edge_fused_kernel(const int* __restrict__ ei) {
    int e = (blockIdx.x * blockDim.x + threadIdx.x) >> 5;
    int lane = threadIdx.x & 31;
    if (e >= EE) return;
    int src = ei[e], dst = ei[EE + e];
    const float4* qr = reinterpret_cast<const float4*>(g_qkvs + (size_t)dst * NFUSE);
    const float4* kr = reinterpret_cast<const float4*>(g_qkvs + (size_t)src * NFUSE + 512);
    const float4* vr = reinterpret_cast<const float4*>(g_qkvs + (size_t)src * NFUSE + 1024);

    float s[4];
#pragma unroll
    for (int h = 0; h < 4; h++) {
        float4 a = qr[h * 32 + lane];
        float4 b = kr[h * 32 + lane];
        s[h] = a.x * b.x + a.y * b.y + a.z * b.z + a.w * b.w;
    }
#pragma unroll
    for (int h = 0; h < 4; h++)
#pragma unroll
        for (int o = 16; o > 0; o >>= 1) s[h] += __shfl_xor_sync(0xffffffffu, s[h], o);

    float ex[4];
#pragma unroll
    for (int h = 0; h < 4; h++)
        ex[h] = expf(s[h] * 0.0883883476483184f);   // 1/sqrt(128)

    if (lane < 4) atomicAdd(&g_den[dst * 4 + lane], ex[lane]);

    float* ar = g_agg + (size_t)dst * 512;
#pragma unroll
    for (int h = 0; h < 4; h++) {
        float4 vv = vr[h * 32 + lane];
        float* p = ar + h * 128 + lane * 4;
        asm volatile("red.global.add.v4.f32 [%0], {%1, %2, %3, %4};"
                     :: "l"(p), "f"(vv.x * ex[h]), "f"(vv.y * ex[h]),
                        "f"(vv.z * ex[h]), "f"(vv.w * ex[h]) : "memory");
    }
}

// ---------------- layernorm ----------------
__device__ __forceinline__ float4 ln_core(float4 vv, int lane,
                                          const float* __restrict__ g,
                                          const float* __restrict__ b) {
    float sum = vv.x + vv.y + vv.z + vv.w;
    float sq = vv.x * vv.x + vv.y * vv.y + vv.z * vv.z + vv.w * vv.w;
#pragma unroll
    for (int o = 16; o > 0; o >>= 1) {
        sum += __shfl_xor_sync(0xffffffffu, sum, o);
        sq  += __shfl_xor_sync(0xffffffffu, sq, o);
    }
    float mu = sum * (1.f / 128.f);
    float var = sq * (1.f / 128.f) - mu * mu;
    float rstd = rsqrtf(var + 1e-5f);
    float4 gv = reinterpret_cast<const float4*>(g)[lane];
    float4 bv = reinterpret_cast<const float4*>(b)[lane];
    float4 o;
    o.x = (vv.x - mu) * rstd * gv.x + bv.x;
    o.y = (vv.y - mu) * rstd * gv.y + bv.y;
    o.z = (vv.z - mu) * rstd * gv.z + bv.z;
    o.w = (vv.w - mu) * rstd * gv.w + bv.w;
    return o;
}

// x1 = LN(x + mean_h(agg_h/den_h) + skip)
__global__ void ln1_kernel(const float* __restrict__ x,
                           const float* __restrict__ g, const float* __restrict__ b) {
    int row = (blockIdx.x * blockDim.x + threadIdx.x) >> 5;
    int lane = threadIdx.x & 31;
    if (row >= NN) return;
    float4 xv = reinterpret_cast<const float4*>(x + (size_t)row * DD)[lane];
    float4 sv = reinterpret_cast<const float4*>(g_qkvs + (size_t)row * NFUSE + 1536)[lane];
    float4 dn = reinterpret_cast<const float4*>(g_den)[row];
    float i0 = dn.x > 0.f ? 0.25f / dn.x : 0.f;
    float i1 = dn.y > 0.f ? 0.25f / dn.y : 0.f;
    float i2 = dn.z > 0.f ? 0.25f / dn.z : 0.f;
    float i3 = dn.w > 0.f ? 0.25f / dn.w : 0.f;
    const float4* ar = reinterpret_cast<const float4*>(g_agg + (size_t)row * 512);
    float4 a0 = ar[lane], a1 = ar[32 + lane], a2 = ar[64 + lane], a3 = ar[96 + lane];
    float4 vv;
    vv.x = xv.x + sv.x + a0.x * i0 + a1.x * i1 + a2.x * i2 + a3.x * i3;
    vv.y = xv.y + sv.y + a0.y * i0 + a1.y * i1 + a2.y * i2 + a3.y * i3;
    vv.z = xv.z + sv.z + a0.z * i0 + a1.z * i1 + a2.z * i2 + a3.z * i3;
    vv.w = xv.w + sv.w + a0.w * i0 + a1.w * i1 + a2.w * i2 + a3.w * i3;
    float4 o = ln_core(vv, lane, g, b);
    reinterpret_cast<float4*>(g_x1 + (size_t)row * DD)[lane] = o;
}

__global__ void ln_add_kernel(const float* __restrict__ a, const float* __restrict__ bb,
                              const float* __restrict__ g, const float* __restrict__ beta,
                              float* __restrict__ out,
                              __nv_bfloat16* __restrict__ oh,
                              __nv_bfloat16* __restrict__ ol) {
    int row = (blockIdx.x * blockDim.x + threadIdx.x) >> 5;
    int lane = threadIdx.x & 31;
    if (row >= NN) return;
    float4 av = reinterpret_cast<const float4*>(a + (size_t)row * DD)[lane];
    float4 bv = reinterpret_cast<const float4*>(bb + (size_t)row * DD)[lane];
    float4 vv = make_float4(av.x + bv.x, av.y + bv.y, av.z + bv.z, av.w + bv.w);
    float4 o = ln_core(vv, lane, g, beta);
    reinterpret_cast<float4*>(out + (size_t)row * DD)[lane] = o;
    if (oh) {
        __nv_bfloat162 h01, l01, h23, l23;
        split2(o.x, o.y, h01, l01);
        split2(o.z, o.w, h23, l23);
        size_t base = (size_t)row * DD + lane * 4;
        *reinterpret_cast<__nv_bfloat162*>(oh + base)     = h01;
        *reinterpret_cast<__nv_bfloat162*>(oh + base + 2) = h23;
        *reinterpret_cast<__nv_bfloat162*>(ol + base)     = l01;
        *reinterpret_cast<__nv_bfloat162*>(ol + base + 2) = l23;
    }
}

// ---------------- launch ----------------
static void* sym(const void* s) { void* p = nullptr; cudaGetSymbolAddress(&p, s); return p; }

extern "C" void kernel_launch(void* const* d_in, const int* in_sizes, int n_in,
                              void* d_out, int out_size)
{
    const float* x    = (const float*)d_in[0];
    const float* te   = (const float*)d_in[1];
    const float* gq_w = (const float*)d_in[2];  const float* gq_b = (const float*)d_in[3];
    const float* gk_w = (const float*)d_in[4];  const float* gk_b = (const float*)d_in[5];
    const float* gv_w = (const float*)d_in[6];  const float* gv_b = (const float*)d_in[7];
    const float* gs_w = (const float*)d_in[8];  const float* gs_b = (const float*)d_in[9];
    // mha_wq/bq, mha_wk/bk dead: softmax over one kv position is exactly 1.
    const float* wv   = (const float*)d_in[14]; const float* bv   = (const float*)d_in[15];
    const float* wo   = (const float*)d_in[16]; const float* bo   = (const float*)d_in[17];
    const float* w1   = (const float*)d_in[18]; const float* b1   = (const float*)d_in[19];
    const float* w2   = (const float*)d_in[20]; const float* b2   = (const float*)d_in[21];
    const float* ln1g = (const float*)d_in[22]; const float* ln1b = (const float*)d_in[23];
    const float* ln2g = (const float*)d_in[24]; const float* ln2b = (const float*)d_in[25];
    const float* ln3g = (const float*)d_in[26]; const float* ln3b = (const float*)d_in[27];
    const int*   ei   = (const int*)d_in[28];
    float* out = (float*)d_out;

    float* qkvs_p = (float*)sym(g_qkvs);
    float* x1_p   = (float*)sym(g_x1);
    float* tout_p = (float*)sym(g_tout);
    float* x2_p   = (float*)sym(g_x2);
    float* ffn_p  = (float*)sym(g_ffn);
    float* bf_p   = (float*)sym(g_bias_f);

    __nv_bfloat16* xh  = (__nv_bfloat16*)sym(g_xh);  __nv_bfloat16* xl  = (__nv_bfloat16*)sym(g_xl);
    __nv_bfloat16* teh = (__nv_bfloat16*)sym(g_teh); __nv_bfloat16* tel = (__nv_bfloat16*)sym(g_tel);
    __nv_bfloat16* tvh = (__nv_bfloat16*)sym(g_tvh); __nv_bfloat16* tvl = (__nv_bfloat16*)sym(g_tvl);
    __nv_bfloat16* x2h = (__nv_bfloat16*)sym(g_x2h); __nv_bfloat16* x2l = (__nv_bfloat16*)sym(g_x2l);
    __nv_bfloat16* hh  = (__nv_bfloat16*)sym(g_hh);  __nv_bfloat16* hl  = (__nv_bfloat16*)sym(g_hl);
    __nv_bfloat16* wfh = (__nv_bfloat16*)sym(g_wfh); __nv_bfloat16* wfl = (__nv_bfloat16*)sym(g_wfl);
    __nv_bfloat16* mvh = (__nv_bfloat16*)sym(g_mvh); __nv_bfloat16* mvl = (__nv_bfloat16*)sym(g_mvl);
    __nv_bfloat16* moh = (__nv_bfloat16*)sym(g_moh); __nv_bfloat16* mol = (__nv_bfloat16*)sym(g_mol);
    __nv_bfloat16* w1h = (__nv_bfloat16*)sym(g_w1h); __nv_bfloat16* w1l = (__nv_bfloat16*)sym(g_w1l);
    __nv_bfloat16* w2h = (__nv_bfloat16*)sym(g_w2h); __nv_bfloat16* w2l = (__nv_bfloat16*)sym(g_w2l);

    cudaFuncSetAttribute(gemm_tc<false, false>,
                         cudaFuncAttributeMaxDynamicSharedMemorySize, SM_TOT);
    cudaFuncSetAttribute(gemm_tc<true, false>,
                         cudaFuncAttributeMaxDynamicSharedMemorySize, SM_TOT);
    cudaFuncSetAttribute(gemm_tc<true, true>,
                         cudaFuncAttributeMaxDynamicSharedMemorySize, SM_TOT);

    const int MB = (NN + 127) / 128;  // 157

    init_kernel<<<(NN * 128 + 255) / 256, 256>>>();
    bias_concat<<<(NFUSE + 255) / 256, 256>>>(gq_b, gk_b, gv_b, gs_b);

    CJs jobs;
    jobs.j[0] = {x,    xh,  xl,  NN * DD / 4};
    jobs.j[1] = {te,   teh, tel, NN * DD / 4};
    jobs.j[2] = {gq_w, wfh,               wfl,               512 * 128 / 4};
    jobs.j[3] = {gk_w, wfh + 512 * 128,   wfl + 512 * 128,   512 * 128 / 4};
    jobs.j[4] = {gv_w, wfh + 1024 * 128,  wfl + 1024 * 128,  512 * 128 / 4};
    jobs.j[5] = {gs_w, wfh + 1536 * 128,  wfl + 1536 * 128,  128 * 128 / 4};
    jobs.j[6] = {wv,   mvh, mvl, 128 * 128 / 4};
    jobs.j[7] = {wo,   moh, mol, 128 * 128 / 4};
    jobs.j[8] = {w1,   w1h, w1l, 512 * 128 / 4};
    jobs.j[9] = {w2,   w2h, w2l, 128 * 512 / 4};
    conv_batch<<<dim3(96, 10), 256>>>(jobs);

    // fused q|k|v|skip projection: [NN,1664] = x @ [1664,128]^T + bias
    gemm_tc<false, false><<<dim3(NFUSE / 128, MB), 256, SM_TOT>>>(
        xh, xl, wfh, wfl, bf_p, qkvs_p, nullptr, nullptr, NN, NFUSE, 128);
    // temporal branch
    gemm_tc<true, false><<<dim3(1, MB), 256, SM_TOT>>>(
        teh, tel, mvh, mvl, bv, nullptr, tvh, tvl, NN, 128, 128);
    gemm_tc<false, false><<<dim3(1, MB), 256, SM_TOT>>>(
        tvh, tvl, moh, mol, bo, tout_p, nullptr, nullptr, NN, 128, 128);

    // graph attention: single fused pass (unnormalized scatter + den)
    edge_fused_kernel<<<EE / 8, 256>>>(ei);

    ln1_kernel<<<(NN + 7) / 8, 256>>>(x, ln1g, ln1b);
    ln_add_kernel<<<(NN + 7) / 8, 256>>>(x1_p, tout_p, ln2g, ln2b, x2_p, x2h, x2l);
    // FFN
    gemm_tc<true, true><<<dim3(4, MB), 256, SM_TOT>>>(
        x2h, x2l, w1h, w1l, b1, nullptr, hh, hl, NN, 512, 128);
    gemm_tc<false, false><<<dim3(1, MB), 256, SM_TOT>>>(
        hh, hl, w2h, w2l, b2, ffn_p, nullptr, nullptr, NN, 128, 512);
    ln_add_kernel<<<(NN + 7) / 8, 256>>>(x2_p, ffn_p, ln3g, ln3b, out, nullptr, nullptr);
}

// round 11
// speedup vs baseline: 1.2483x; 1.2483x over previous
#include <cuda_runtime.h>
#include <cuda_bf16.h>
#include <math.h>
#include <math_constants.h>
#include <stdint.h>

#define NN 20000
#define EE 160000
#define DD 128
#define NFUSE 1664   // 512(q)+512(k)+512(v)+128(skip)

// ---------------- scratch (static device globals; no allocation) ----------------
__device__ float g_qkvs[NN * NFUSE];   // fused q|k|v|skip, row stride 1664
__device__ float g_gout[NN * DD];      // normalized head-mean graph attention output
__device__ float g_x1[NN * DD];
__device__ float g_tout[NN * DD];
__device__ float g_x2[NN * DD];
__device__ float g_ffn[NN * DD];
__device__ float g_bias_f[NFUSE];
// CSR scratch
__device__ int g_deg[NN];
__device__ int g_rowptr[NN + 1];
__device__ int g_cursor[NN];
__device__ int g_blocksum[32];
__device__ int g_ssrc[EE];

// bf16 hi/lo operand buffers
__device__ __nv_bfloat16 g_xh[NN * DD],  g_xl[NN * DD];
__device__ __nv_bfloat16 g_teh[NN * DD], g_tel[NN * DD];
__device__ __nv_bfloat16 g_tvh[NN * DD], g_tvl[NN * DD];
__device__ __nv_bfloat16 g_x2h[NN * DD], g_x2l[NN * DD];
__device__ __nv_bfloat16 g_hh[NN * 512], g_hl[NN * 512];
__device__ __nv_bfloat16 g_wfh[NFUSE * 128], g_wfl[NFUSE * 128];
__device__ __nv_bfloat16 g_mvh[128 * 128], g_mvl[128 * 128];
__device__ __nv_bfloat16 g_moh[128 * 128], g_mol[128 * 128];
__device__ __nv_bfloat16 g_w1h[512 * 128], g_w1l[512 * 128];
__device__ __nv_bfloat16 g_w2h[128 * 512], g_w2l[128 * 512];

// ---------------- helpers ----------------
__device__ __forceinline__ void split2(float x, float y,
                                       __nv_bfloat162& h, __nv_bfloat162& l) {
    __nv_bfloat16 hx = __float2bfloat16(x);
    __nv_bfloat16 hy = __float2bfloat16(y);
    __nv_bfloat16 lx = __float2bfloat16(x - __bfloat162float(hx));
    __nv_bfloat16 ly = __float2bfloat16(y - __bfloat162float(hy));
    h = __halves2bfloat162(hx, hy);
    l = __halves2bfloat162(lx, ly);
}

__device__ __forceinline__ void mma_bf16(float* c, const uint32_t* a, const uint32_t* b) {
    asm volatile(
        "mma.sync.aligned.m16n8k16.row.col.f32.bf16.bf16.f32 "
        "{%0,%1,%2,%3}, {%4,%5,%6,%7}, {%8,%9}, {%0,%1,%2,%3};"
        : "+f"(c[0]), "+f"(c[1]), "+f"(c[2]), "+f"(c[3])
        : "r"(a[0]), "r"(a[1]), "r"(a[2]), "r"(a[3]), "r"(b[0]), "r"(b[1]));
}

__device__ __forceinline__ void ldsm_x4(uint32_t& r0, uint32_t& r1, uint32_t& r2,
                                        uint32_t& r3, uint32_t addr) {
    asm volatile("ldmatrix.sync.aligned.m8n8.x4.shared.b16 {%0,%1,%2,%3}, [%4];"
                 : "=r"(r0), "=r"(r1), "=r"(r2), "=r"(r3) : "r"(addr));
}

__device__ __forceinline__ void cp16(uint32_t dst, const void* src) {
    asm volatile("cp.async.cg.shared.global [%0], [%1], 16;" :: "r"(dst), "l"(src));
}

// ---------------- misc small kernels ----------------
__global__ void bias_concat(const float* a, const float* b,
                            const float* c, const float* d) {
    int i = blockIdx.x * blockDim.x + threadIdx.x;
    if (i < 512) g_bias_f[i] = a[i];
    else if (i < 1024) g_bias_f[i] = b[i - 512];
    else if (i < 1536) g_bias_f[i] = c[i - 1024];
    else if (i < NFUSE) g_bias_f[i] = d[i - 1536];
}

// ---------------- batched fp32 -> bf16 hi/lo conversion ----------------
struct CJ { const float* s; __nv_bfloat16* h; __nv_bfloat16* l; int n4; };
struct CJs { CJ j[10]; };

__global__ void conv_batch(CJs jobs) {
    CJ job = jobs.j[blockIdx.y];
    int stride = gridDim.x * blockDim.x;
    for (int i = blockIdx.x * blockDim.x + threadIdx.x; i < job.n4; i += stride) {
        float4 v = reinterpret_cast<const float4*>(job.s)[i];
        __nv_bfloat162 h01, l01, h23, l23;
        split2(v.x, v.y, h01, l01);
        split2(v.z, v.w, h23, l23);
        reinterpret_cast<__nv_bfloat162*>(job.h)[2 * i]     = h01;
        reinterpret_cast<__nv_bfloat162*>(job.h)[2 * i + 1] = h23;
        reinterpret_cast<__nv_bfloat162*>(job.l)[2 * i]     = l01;
        reinterpret_cast<__nv_bfloat162*>(job.l)[2 * i + 1] = l23;
    }
}

// ---------------- CSR build ----------------
__global__ void deg_zero_kernel() {
    int i = blockIdx.x * blockDim.x + threadIdx.x;
    if (i < NN) g_deg[i] = 0;
}
__global__ void hist_kernel(const int* __restrict__ ei) {
    int e = blockIdx.x * blockDim.x + threadIdx.x;
    if (e < EE) atomicAdd(&g_deg[ei[EE + e]], 1);
}
// block-level exclusive scan (1024 per block); partials + block totals
__global__ void scanA_kernel() {
    int t = threadIdx.x, b = blockIdx.x;
    int idx = b * 1024 + t;
    int v = (idx < NN) ? g_deg[idx] : 0;
    int lane = t & 31, wid = t >> 5;
    int x = v;
#pragma unroll
    for (int o = 1; o < 32; o <<= 1) {
        int y = __shfl_up_sync(0xffffffffu, x, o);
        if (lane >= o) x += y;
    }
    __shared__ int wsum[32];
    if (lane == 31) wsum[wid] = x;
    __syncthreads();
    if (wid == 0) {
        int w = wsum[lane];
#pragma unroll
        for (int o = 1; o < 32; o <<= 1) {
            int y = __shfl_up_sync(0xffffffffu, w, o);
            if (lane >= o) w += y;
        }
        wsum[lane] = w;
    }
    __syncthreads();
    int incl = x + (wid > 0 ? wsum[wid - 1] : 0);
    if (idx < NN) g_rowptr[idx] = incl - v;   // exclusive, local to block
    if (t == 1023) g_blocksum[b] = incl;
}
__global__ void scanB_kernel(int nblk) {
    if (threadIdx.x == 0) {
        int run = 0;
        for (int i = 0; i < nblk; i++) {
            int t = g_blocksum[i];
            g_blocksum[i] = run;
            run += t;
        }
    }
}
__global__ void scanC_kernel() {
    int i = blockIdx.x * blockDim.x + threadIdx.x;
    if (i < NN) {
        int r = g_rowptr[i] + g_blocksum[i >> 10];
        g_rowptr[i] = r;
        g_cursor[i] = r;
    }
    if (i == 0) g_rowptr[NN] = EE;
}
__global__ void fill_kernel(const int* __restrict__ ei) {
    int e = blockIdx.x * blockDim.x + threadIdx.x;
    if (e >= EE) return;
    int dst = ei[EE + e];
    int pos = atomicAdd(&g_cursor[dst], 1);
    g_ssrc[pos] = ei[e];
}

// ---------------- per-dst edge aggregation (no atomics) ----------------
// warp per dst node: q[dst] loaded once; stream incoming edges' k/v;
// softmax (shift-free: alpha is O(0.01)) normalized in-register;
// write head-mean gout[dst][128] once.
__global__ void edge_dst_kernel() {
    int row = (blockIdx.x * blockDim.x + threadIdx.x) >> 5;
    int lane = threadIdx.x & 31;
    if (row >= NN) return;
    const float4* qr = reinterpret_cast<const float4*>(g_qkvs + (size_t)row * NFUSE);
    float4 q4[4];
#pragma unroll
    for (int h = 0; h < 4; h++) q4[h] = qr[h * 32 + lane];

    float4 acc[4];
    float den[4];
#pragma unroll
    for (int h = 0; h < 4; h++) {
        acc[h] = make_float4(0.f, 0.f, 0.f, 0.f);
        den[h] = 0.f;
    }

    int p0 = g_rowptr[row], p1 = g_rowptr[row + 1];
    for (int p = p0; p < p1; p++) {
        int src = g_ssrc[p];
        const float4* kr = reinterpret_cast<const float4*>(
            g_qkvs + (size_t)src * NFUSE + 512);
        const float4* vr = kr + 128;   // +512 floats
        float4 k4[4], v4[4];
#pragma unroll
        for (int h = 0; h < 4; h++) { k4[h] = kr[h * 32 + lane]; v4[h] = vr[h * 32 + lane]; }
        float s[4];
#pragma unroll
        for (int h = 0; h < 4; h++)
            s[h] = q4[h].x * k4[h].x + q4[h].y * k4[h].y
                 + q4[h].z * k4[h].z + q4[h].w * k4[h].w;
#pragma unroll
        for (int h = 0; h < 4; h++)
#pragma unroll
            for (int o = 16; o > 0; o >>= 1)
                s[h] += __shfl_xor_sync(0xffffffffu, s[h], o);
#pragma unroll
        for (int h = 0; h < 4; h++) {
            float ex = expf(s[h] * 0.0883883476483184f);  // 1/sqrt(128)
            den[h] += ex;
            acc[h].x += ex * v4[h].x; acc[h].y += ex * v4[h].y;
            acc[h].z += ex * v4[h].z; acc[h].w += ex * v4[h].w;
        }
    }

    float4 o = make_float4(0.f, 0.f, 0.f, 0.f);
#pragma unroll
    for (int h = 0; h < 4; h++) {
        if (den[h] > 0.f) {
            float inv = 0.25f / den[h];
            o.x += acc[h].x * inv; o.y += acc[h].y * inv;
            o.z += acc[h].z * inv; o.w += acc[h].w * inv;
        }
    }
    reinterpret_cast<float4*>(g_gout + (size_t)row * DD)[lane] = o;
}

// ---------------- bf16x3 mma.sync GEMM (R9 config: 128x64, single-shot K=128) ----------------
#define LDK 136   // 128 + 8 pad
#define OA_H 0
#define OA_L (128 * LDK * 2)
#define OW_H (2 * 128 * LDK * 2)
#define OW_L (OW_H + 64 * LDK * 2)
#define SM_TOT (OW_L + 64 * LDK * 2)    // 104448 bytes

template<bool BF16OUT, bool RELU>
__global__ __launch_bounds__(256) void gemm_tc(
    const __nv_bfloat16* __restrict__ Ah, const __nv_bfloat16* __restrict__ Al,
    const __nv_bfloat16* __restrict__ Wh, const __nv_bfloat16* __restrict__ Wl,
    const float* __restrict__ bias,
    float* __restrict__ Cf, __nv_bfloat16* __restrict__ Ch,
    __nv_bfloat16* __restrict__ Cl,
    int M, int Nc, int K)
{
    extern __shared__ char smem[];
    const uint32_t smb = (uint32_t)__cvta_generic_to_shared(smem);

    const int tid  = threadIdx.x;
    const int lane = tid & 31;
    const int w    = tid >> 5;
    const int wm   = w & 3;
    const int wn   = w >> 2;
    const int bm   = blockIdx.y * 128;
    const int bn   = blockIdx.x * 64;

    const int lrow = lane & 7;
    const int quad = lane >> 3;
    const int a_roff = lrow + ((quad & 1) << 3);
    const int a_coff = (quad >> 1) << 3;
    const int b_roff = lrow + ((quad >> 1) << 3);
    const int b_coff = (quad & 1) << 3;

    float acc[2][4][4];
#pragma unroll
    for (int i = 0; i < 2; i++)
#pragma unroll
        for (int j = 0; j < 4; j++)
#pragma unroll
            for (int t = 0; t < 4; t++) acc[i][j][t] = 0.f;

    for (int kt = 0; kt < K; kt += 128) {
        if (kt > 0) __syncthreads();
#pragma unroll
        for (int it = 0; it < 8; it++) {
            int i = tid + it * 256;
            int row = i >> 4, c16 = i & 15;
            int ga = bm + row; if (ga >= M) ga = M - 1;
            size_t goff = (size_t)ga * K + kt + c16 * 8;
            uint32_t d = smb + (row * LDK + c16 * 8) * 2;
            cp16(d + OA_H, Ah + goff);
            cp16(d + OA_L, Al + goff);
        }
#pragma unroll
        for (int it = 0; it < 4; it++) {
            int i = tid + it * 256;
            int row = i >> 4, c16 = i & 15;
            size_t goff = (size_t)(bn + row) * K + kt + c16 * 8;
            uint32_t d = smb + (row * LDK + c16 * 8) * 2;
            cp16(d + OW_H, Wh + goff);
            cp16(d + OW_L, Wl + goff);
        }
        asm volatile("cp.async.commit_group;");
        asm volatile("cp.async.wait_group 0;");
        __syncthreads();

#pragma unroll
        for (int ks = 0; ks < 128; ks += 16) {
            uint32_t ahf[2][4], alf[2][4], bhf[4][2], blf[4][2];
#pragma unroll
            for (int i = 0; i < 2; i++) {
                uint32_t off = (uint32_t)(((wm * 32 + i * 16 + a_roff) * LDK
                                           + ks + a_coff) * 2);
                ldsm_x4(ahf[i][0], ahf[i][1], ahf[i][2], ahf[i][3], smb + OA_H + off);
                ldsm_x4(alf[i][0], alf[i][1], alf[i][2], alf[i][3], smb + OA_L + off);
            }
#pragma unroll
            for (int jp = 0; jp < 2; jp++) {
                uint32_t off = (uint32_t)(((wn * 32 + jp * 16 + b_roff) * LDK
                                           + ks + b_coff) * 2);
                ldsm_x4(bhf[2 * jp][0], bhf[2 * jp][1],
                        bhf[2 * jp + 1][0], bhf[2 * jp + 1][1], smb + OW_H + off);
                ldsm_x4(blf[2 * jp][0], blf[2 * jp][1],
                        blf[2 * jp + 1][0], blf[2 * jp + 1][1], smb + OW_L + off);
            }
#pragma unroll
            for (int i = 0; i < 2; i++)
#pragma unroll
                for (int j = 0; j < 4; j++) {
                    mma_bf16(acc[i][j], ahf[i], bhf[j]);
                    mma_bf16(acc[i][j], ahf[i], blf[j]);
                    mma_bf16(acc[i][j], alf[i], bhf[j]);
                }
        }
    }

    const int qr = lane >> 2;
    const int kq = (lane & 3) * 2;
#pragma unroll
    for (int i = 0; i < 2; i++) {
        int r0 = bm + wm * 32 + i * 16 + qr;
#pragma unroll
        for (int j = 0; j < 4; j++) {
            int c = bn + wn * 32 + j * 8 + kq;
            float b0 = bias[c], b1 = bias[c + 1];
            float v0 = acc[i][j][0] + b0, v1 = acc[i][j][1] + b1;
            float v2 = acc[i][j][2] + b0, v3 = acc[i][j][3] + b1;
            if (RELU) {
                v0 = fmaxf(v0, 0.f); v1 = fmaxf(v1, 0.f);
                v2 = fmaxf(v2, 0.f); v3 = fmaxf(v3, 0.f);
            }
            if (!BF16OUT) {
                if (r0 < M)
                    *reinterpret_cast<float2*>(Cf + (size_t)r0 * Nc + c) =
                        make_float2(v0, v1);
                if (r0 + 8 < M)
                    *reinterpret_cast<float2*>(Cf + (size_t)(r0 + 8) * Nc + c) =
                        make_float2(v2, v3);
            } else {
                __nv_bfloat162 hh2, ll2;
                if (r0 < M) {
                    split2(v0, v1, hh2, ll2);
                    *reinterpret_cast<__nv_bfloat162*>(Ch + (size_t)r0 * Nc + c) = hh2;
                    *reinterpret_cast<__nv_bfloat162*>(Cl + (size_t)r0 * Nc + c) = ll2;
                }
                if (r0 + 8 < M) {
                    split2(v2, v3, hh2, ll2);
                    *reinterpret_cast<__nv_bfloat162*>(Ch + (size_t)(r0 + 8) * Nc + c) = hh2;
                    *reinterpret_cast<__nv_bfloat162*>(Cl + (size_t)(r0 + 8) * Nc + c) = ll2;
                }
            }
        }
    }
}

// ---------------- layernorm ----------------
__device__ __forceinline__ float4 ln_core(float4 vv, int lane,
                                          const float* __restrict__ g,
                                          const float* __restrict__ b) {
    float sum = vv.x + vv.y + vv.z + vv.w;
    float sq = vv.x * vv.x + vv.y * vv.y + vv.z * vv.z + vv.w * vv.w;
#pragma unroll
    for (int o = 16; o > 0; o >>= 1) {
        sum += __shfl_xor_sync(0xffffffffu, sum, o);
        sq  += __shfl_xor_sync(0xffffffffu, sq, o);
    }
    float mu = sum * (1.f / 128.f);
    float var = sq * (1.f / 128.f) - mu * mu;
    float rstd = rsqrtf(var + 1e-5f);
    float4 gv = reinterpret_cast<const float4*>(g)[lane];
    float4 bv = reinterpret_cast<const float4*>(b)[lane];
    float4 o;
    o.x = (vv.x - mu) * rstd * gv.x + bv.x;
    o.y = (vv.y - mu) * rstd * gv.y + bv.y;
    o.z = (vv.z - mu) * rstd * gv.z + bv.z;
    o.w = (vv.w - mu) * rstd * gv.w + bv.w;
    return o;
}

// x1 = LN(x + gout + skip)
__global__ void ln1_kernel(const float* __restrict__ x,
                           const float* __restrict__ g, const float* __restrict__ b) {
    int row = (blockIdx.x * blockDim.x + threadIdx.x) >> 5;
    int lane = threadIdx.x & 31;
    if (row >= NN) return;
    float4 xv = reinterpret_cast<const float4*>(x + (size_t)row * DD)[lane];
    float4 sv = reinterpret_cast<const float4*>(g_qkvs + (size_t)row * NFUSE + 1536)[lane];
    float4 gv = reinterpret_cast<const float4*>(g_gout + (size_t)row * DD)[lane];
    float4 vv = make_float4(xv.x + sv.x + gv.x, xv.y + sv.y + gv.y,
                            xv.z + sv.z + gv.z, xv.w + sv.w + gv.w);
    float4 o = ln_core(vv, lane, g, b);
    reinterpret_cast<float4*>(g_x1 + (size_t)row * DD)[lane] = o;
}

__global__ void ln_add_kernel(const float* __restrict__ a, const float* __restrict__ bb,
                              const float* __restrict__ g, const float* __restrict__ beta,
                              float* __restrict__ out,
                              __nv_bfloat16* __restrict__ oh,
                              __nv_bfloat16* __restrict__ ol) {
    int row = (blockIdx.x * blockDim.x + threadIdx.x) >> 5;
    int lane = threadIdx.x & 31;
    if (row >= NN) return;
    float4 av = reinterpret_cast<const float4*>(a + (size_t)row * DD)[lane];
    float4 bv = reinterpret_cast<const float4*>(bb + (size_t)row * DD)[lane];
    float4 vv = make_float4(av.x + bv.x, av.y + bv.y, av.z + bv.z, av.w + bv.w);
    float4 o = ln_core(vv, lane, g, beta);
    reinterpret_cast<float4*>(out + (size_t)row * DD)[lane] = o;
    if (oh) {
        __nv_bfloat162 h01, l01, h23, l23;
        split2(o.x, o.y, h01, l01);
        split2(o.z, o.w, h23, l23);
        size_t base = (size_t)row * DD + lane * 4;
        *reinterpret_cast<__nv_bfloat162*>(oh + base)     = h01;
        *reinterpret_cast<__nv_bfloat162*>(oh + base + 2) = h23;
        *reinterpret_cast<__nv_bfloat162*>(ol + base)     = l01;
        *reinterpret_cast<__nv_bfloat162*>(ol + base + 2) = l23;
    }
}

// ---------------- launch ----------------
static void* sym(const void* s) { void* p = nullptr; cudaGetSymbolAddress(&p, s); return p; }

extern "C" void kernel_launch(void* const* d_in, const int* in_sizes, int n_in,
                              void* d_out, int out_size)
{
    const float* x    = (const float*)d_in[0];
    const float* te   = (const float*)d_in[1];
    const float* gq_w = (const float*)d_in[2];  const float* gq_b = (const float*)d_in[3];
    const float* gk_w = (const float*)d_in[4];  const float* gk_b = (const float*)d_in[5];
    const float* gv_w = (const float*)d_in[6];  const float* gv_b = (const float*)d_in[7];
    const float* gs_w = (const float*)d_in[8];  const float* gs_b = (const float*)d_in[9];
    // mha_wq/bq, mha_wk/bk dead: softmax over one kv position is exactly 1.
    const float* wv   = (const float*)d_in[14]; const float* bv   = (const float*)d_in[15];
    const float* wo   = (const float*)d_in[16]; const float* bo   = (const float*)d_in[17];
    const float* w1   = (const float*)d_in[18]; const float* b1   = (const float*)d_in[19];
    const float* w2   = (const float*)d_in[20]; const float* b2   = (const float*)d_in[21];
    const float* ln1g = (const float*)d_in[22]; const float* ln1b = (const float*)d_in[23];
    const float* ln2g = (const float*)d_in[24]; const float* ln2b = (const float*)d_in[25];
    const float* ln3g = (const float*)d_in[26]; const float* ln3b = (const float*)d_in[27];
    const int*   ei   = (const int*)d_in[28];
    float* out = (float*)d_out;

    float* qkvs_p = (float*)sym(g_qkvs);
    float* x1_p   = (float*)sym(g_x1);
    float* tout_p = (float*)sym(g_tout);
    float* x2_p   = (float*)sym(g_x2);
    float* ffn_p  = (float*)sym(g_ffn);
    float* bf_p   = (float*)sym(g_bias_f);

    __nv_bfloat16* xh  = (__nv_bfloat16*)sym(g_xh);  __nv_bfloat16* xl  = (__nv_bfloat16*)sym(g_xl);
    __nv_bfloat16* teh = (__nv_bfloat16*)sym(g_teh); __nv_bfloat16* tel = (__nv_bfloat16*)sym(g_tel);
    __nv_bfloat16* tvh = (__nv_bfloat16*)sym(g_tvh); __nv_bfloat16* tvl = (__nv_bfloat16*)sym(g_tvl);
    __nv_bfloat16* x2h = (__nv_bfloat16*)sym(g_x2h); __nv_bfloat16* x2l = (__nv_bfloat16*)sym(g_x2l);
    __nv_bfloat16* hh  = (__nv_bfloat16*)sym(g_hh);  __nv_bfloat16* hl  = (__nv_bfloat16*)sym(g_hl);
    __nv_bfloat16* wfh = (__nv_bfloat16*)sym(g_wfh); __nv_bfloat16* wfl = (__nv_bfloat16*)sym(g_wfl);
    __nv_bfloat16* mvh = (__nv_bfloat16*)sym(g_mvh); __nv_bfloat16* mvl = (__nv_bfloat16*)sym(g_mvl);
    __nv_bfloat16* moh = (__nv_bfloat16*)sym(g_moh); __nv_bfloat16* mol = (__nv_bfloat16*)sym(g_mol);
    __nv_bfloat16* w1h = (__nv_bfloat16*)sym(g_w1h); __nv_bfloat16* w1l = (__nv_bfloat16*)sym(g_w1l);
    __nv_bfloat16* w2h = (__nv_bfloat16*)sym(g_w2h); __nv_bfloat16* w2l = (__nv_bfloat16*)sym(g_w2l);

    cudaFuncSetAttribute(gemm_tc<false, false>,
                         cudaFuncAttributeMaxDynamicSharedMemorySize, SM_TOT);
    cudaFuncSetAttribute(gemm_tc<true, false>,
                         cudaFuncAttributeMaxDynamicSharedMemorySize, SM_TOT);
    cudaFuncSetAttribute(gemm_tc<true, true>,
                         cudaFuncAttributeMaxDynamicSharedMemorySize, SM_TOT);

    const int MB = (NN + 127) / 128;   // 157
    const int NSCAN = (NN + 1023) / 1024;  // 20

    bias_concat<<<(NFUSE + 255) / 256, 256>>>(gq_b, gk_b, gv_b, gs_b);

    // CSR build (depends only on ei)
    deg_zero_kernel<<<(NN + 255) / 256, 256>>>();
    hist_kernel<<<(EE + 255) / 256, 256>>>(ei);
    scanA_kernel<<<NSCAN, 1024>>>();
    scanB_kernel<<<1, 32>>>(NSCAN);
    scanC_kernel<<<(NN + 255) / 256, 256>>>();
    fill_kernel<<<(EE + 255) / 256, 256>>>(ei);

    CJs jobs;
    jobs.j[0] = {x,    xh,  xl,  NN * DD / 4};
    jobs.j[1] = {te,   teh, tel, NN * DD / 4};
    jobs.j[2] = {gq_w, wfh,               wfl,               512 * 128 / 4};
    jobs.j[3] = {gk_w, wfh + 512 * 128,   wfl + 512 * 128,   512 * 128 / 4};
    jobs.j[4] = {gv_w, wfh + 1024 * 128,  wfl + 1024 * 128,  512 * 128 / 4};
    jobs.j[5] = {gs_w, wfh + 1536 * 128,  wfl + 1536 * 128,  128 * 128 / 4};
    jobs.j[6] = {wv,   mvh, mvl, 128 * 128 / 4};
    jobs.j[7] = {wo,   moh, mol, 128 * 128 / 4};
    jobs.j[8] = {w1,   w1h, w1l, 512 * 128 / 4};
    jobs.j[9] = {w2,   w2h, w2l, 128 * 512 / 4};
    conv_batch<<<dim3(96, 10), 256>>>(jobs);

    // fused q|k|v|skip projection: [NN,1664] = x @ [1664,128]^T + bias
    gemm_tc<false, false><<<dim3(NFUSE / 64, MB), 256, SM_TOT>>>(
        xh, xl, wfh, wfl, bf_p, qkvs_p, nullptr, nullptr, NN, NFUSE, 128);
    // temporal branch
    gemm_tc<true, false><<<dim3(2, MB), 256, SM_TOT>>>(
        teh, tel, mvh, mvl, bv, nullptr, tvh, tvl, NN, 128, 128);
    gemm_tc<false, false><<<dim3(2, MB), 256, SM_TOT>>>(
        tvh, tvl, moh, mol, bo, tout_p, nullptr, nullptr, NN, 128, 128);

    // graph attention: warp-per-dst, register accumulation, no atomics
    edge_dst_kernel<<<(NN + 7) / 8, 256>>>();

    ln1_kernel<<<(NN + 7) / 8, 256>>>(x, ln1g, ln1b);
    ln_add_kernel<<<(NN + 7) / 8, 256>>>(x1_p, tout_p, ln2g, ln2b, x2_p, x2h, x2l);
    // FFN
    gemm_tc<true, true><<<dim3(8, MB), 256, SM_TOT>>>(
        x2h, x2l, w1h, w1l, b1, nullptr, hh, hl, NN, 512, 128);
    gemm_tc<false, false><<<dim3(2, MB), 256, SM_TOT>>>(
        hh, hl, w2h, w2l, b2, ffn_p, nullptr, nullptr, NN, 128, 512);
    ln_add_kernel<<<(NN + 7) / 8, 256>>>(x2_p, ffn_p, ln3g, ln3b, out, nullptr, nullptr);
}

// round 12
// speedup vs baseline: 1.2892x; 1.0327x over previous
#include <cuda_runtime.h>
#include <cuda_bf16.h>
#include <math.h>
#include <math_constants.h>
#include <stdint.h>

#define NN 20000
#define EE 160000
#define DD 128
#define NFUSE 1664   // 512(q)+512(k)+512(v)+128(skip)

// ---------------- scratch (static device globals; no allocation) ----------------
__device__ float g_qkvs[NN * NFUSE];   // fused q|k|v|skip, row stride 1664
__device__ float g_gout[NN * DD];      // normalized head-mean graph attention output
__device__ float g_x1[NN * DD];
__device__ float g_tout[NN * DD];
__device__ float g_x2[NN * DD];
__device__ float g_ffn[NN * DD];
__device__ float g_bias_f[NFUSE];
// CSR scratch
__device__ int g_deg[NN];
__device__ int g_rowptr[NN + 1];
__device__ int g_cursor[NN];
__device__ int g_blocksum[32];
__device__ int g_ssrc[EE];

// bf16 hi/lo operand buffers
__device__ __nv_bfloat16 g_xh[NN * DD],  g_xl[NN * DD];
__device__ __nv_bfloat16 g_teh[NN * DD], g_tel[NN * DD];
__device__ __nv_bfloat16 g_tvh[NN * DD], g_tvl[NN * DD];
__device__ __nv_bfloat16 g_x2h[NN * DD], g_x2l[NN * DD];
__device__ __nv_bfloat16 g_hh[NN * 512], g_hl[NN * 512];
__device__ __nv_bfloat16 g_wfh[NFUSE * 128], g_wfl[NFUSE * 128];
__device__ __nv_bfloat16 g_mvh[128 * 128], g_mvl[128 * 128];
__device__ __nv_bfloat16 g_moh[128 * 128], g_mol[128 * 128];
__device__ __nv_bfloat16 g_w1h[512 * 128], g_w1l[512 * 128];
__device__ __nv_bfloat16 g_w2h[128 * 512], g_w2l[128 * 512];

// ---------------- helpers ----------------
__device__ __forceinline__ void split2(float x, float y,
                                       __nv_bfloat162& h, __nv_bfloat162& l) {
    __nv_bfloat16 hx = __float2bfloat16(x);
    __nv_bfloat16 hy = __float2bfloat16(y);
    __nv_bfloat16 lx = __float2bfloat16(x - __bfloat162float(hx));
    __nv_bfloat16 ly = __float2bfloat16(y - __bfloat162float(hy));
    h = __halves2bfloat162(hx, hy);
    l = __halves2bfloat162(lx, ly);
}

__device__ __forceinline__ void mma_bf16(float* c, const uint32_t* a, const uint32_t* b) {
    asm volatile(
        "mma.sync.aligned.m16n8k16.row.col.f32.bf16.bf16.f32 "
        "{%0,%1,%2,%3}, {%4,%5,%6,%7}, {%8,%9}, {%0,%1,%2,%3};"
        : "+f"(c[0]), "+f"(c[1]), "+f"(c[2]), "+f"(c[3])
        : "r"(a[0]), "r"(a[1]), "r"(a[2]), "r"(a[3]), "r"(b[0]), "r"(b[1]));
}

__device__ __forceinline__ void ldsm_x4(uint32_t& r0, uint32_t& r1, uint32_t& r2,
                                        uint32_t& r3, uint32_t addr) {
    asm volatile("ldmatrix.sync.aligned.m8n8.x4.shared.b16 {%0,%1,%2,%3}, [%4];"
                 : "=r"(r0), "=r"(r1), "=r"(r2), "=r"(r3) : "r"(addr));
}

__device__ __forceinline__ void cp16(uint32_t dst, const void* src) {
    asm volatile("cp.async.cg.shared.global [%0], [%1], 16;" :: "r"(dst), "l"(src));
}

// ---------------- misc small kernels ----------------
__global__ void bias_concat(const float* a, const float* b,
                            const float* c, const float* d) {
    int i = blockIdx.x * blockDim.x + threadIdx.x;
    if (i < 512) g_bias_f[i] = a[i];
    else if (i < 1024) g_bias_f[i] = b[i - 512];
    else if (i < 1536) g_bias_f[i] = c[i - 1024];
    else if (i < NFUSE) g_bias_f[i] = d[i - 1536];
}

// ---------------- batched fp32 -> bf16 hi/lo conversion ----------------
struct CJ { const float* s; __nv_bfloat16* h; __nv_bfloat16* l; int n4; };
struct CJs { CJ j[10]; };

__global__ void conv_batch(CJs jobs) {
    CJ job = jobs.j[blockIdx.y];
    int stride = gridDim.x * blockDim.x;
    for (int i = blockIdx.x * blockDim.x + threadIdx.x; i < job.n4; i += stride) {
        float4 v = reinterpret_cast<const float4*>(job.s)[i];
        __nv_bfloat162 h01, l01, h23, l23;
        split2(v.x, v.y, h01, l01);
        split2(v.z, v.w, h23, l23);
        reinterpret_cast<__nv_bfloat162*>(job.h)[2 * i]     = h01;
        reinterpret_cast<__nv_bfloat162*>(job.h)[2 * i + 1] = h23;
        reinterpret_cast<__nv_bfloat162*>(job.l)[2 * i]     = l01;
        reinterpret_cast<__nv_bfloat162*>(job.l)[2 * i + 1] = l23;
    }
}

// ---------------- CSR build ----------------
__global__ void deg_zero_kernel() {
    int i = blockIdx.x * blockDim.x + threadIdx.x;
    if (i < NN) g_deg[i] = 0;
}
__global__ void hist_kernel(const int* __restrict__ ei) {
    int e = blockIdx.x * blockDim.x + threadIdx.x;
    if (e < EE) atomicAdd(&g_deg[ei[EE + e]], 1);
}
__global__ void scanA_kernel() {
    int t = threadIdx.x, b = blockIdx.x;
    int idx = b * 1024 + t;
    int v = (idx < NN) ? g_deg[idx] : 0;
    int lane = t & 31, wid = t >> 5;
    int x = v;
#pragma unroll
    for (int o = 1; o < 32; o <<= 1) {
        int y = __shfl_up_sync(0xffffffffu, x, o);
        if (lane >= o) x += y;
    }
    __shared__ int wsum[32];
    if (lane == 31) wsum[wid] = x;
    __syncthreads();
    if (wid == 0) {
        int w = wsum[lane];
#pragma unroll
        for (int o = 1; o < 32; o <<= 1) {
            int y = __shfl_up_sync(0xffffffffu, w, o);
            if (lane >= o) w += y;
        }
        wsum[lane] = w;
    }
    __syncthreads();
    int incl = x + (wid > 0 ? wsum[wid - 1] : 0);
    if (idx < NN) g_rowptr[idx] = incl - v;
    if (t == 1023) g_blocksum[b] = incl;
}
__global__ void scanB_kernel(int nblk) {
    if (threadIdx.x == 0) {
        int run = 0;
        for (int i = 0; i < nblk; i++) {
            int t = g_blocksum[i];
            g_blocksum[i] = run;
            run += t;
        }
    }
}
__global__ void scanC_kernel() {
    int i = blockIdx.x * blockDim.x + threadIdx.x;
    if (i < NN) {
        int r = g_rowptr[i] + g_blocksum[i >> 10];
        g_rowptr[i] = r;
        g_cursor[i] = r;
    }
    if (i == 0) g_rowptr[NN] = EE;
}
__global__ void fill_kernel(const int* __restrict__ ei) {
    int e = blockIdx.x * blockDim.x + threadIdx.x;
    if (e >= EE) return;
    int dst = ei[EE + e];
    int pos = atomicAdd(&g_cursor[dst], 1);
    g_ssrc[pos] = ei[e];
}

// ---------------- per-dst edge aggregation (no atomics) ----------------
__global__ void edge_dst_kernel() {
    int row = (blockIdx.x * blockDim.x + threadIdx.x) >> 5;
    int lane = threadIdx.x & 31;
    if (row >= NN) return;
    const float4* qr = reinterpret_cast<const float4*>(g_qkvs + (size_t)row * NFUSE);
    float4 q4[4];
#pragma unroll
    for (int h = 0; h < 4; h++) q4[h] = qr[h * 32 + lane];

    float4 acc[4];
    float den[4];
#pragma unroll
    for (int h = 0; h < 4; h++) {
        acc[h] = make_float4(0.f, 0.f, 0.f, 0.f);
        den[h] = 0.f;
    }

    int p0 = g_rowptr[row], p1 = g_rowptr[row + 1];
    for (int p = p0; p < p1; p++) {
        int src = g_ssrc[p];
        const float4* kr = reinterpret_cast<const float4*>(
            g_qkvs + (size_t)src * NFUSE + 512);
        const float4* vr = kr + 128;
        float4 k4[4], v4[4];
#pragma unroll
        for (int h = 0; h < 4; h++) { k4[h] = kr[h * 32 + lane]; v4[h] = vr[h * 32 + lane]; }
        float s[4];
#pragma unroll
        for (int h = 0; h < 4; h++)
            s[h] = q4[h].x * k4[h].x + q4[h].y * k4[h].y
                 + q4[h].z * k4[h].z + q4[h].w * k4[h].w;
#pragma unroll
        for (int h = 0; h < 4; h++)
#pragma unroll
            for (int o = 16; o > 0; o >>= 1)
                s[h] += __shfl_xor_sync(0xffffffffu, s[h], o);
#pragma unroll
        for (int h = 0; h < 4; h++) {
            float ex = expf(s[h] * 0.0883883476483184f);
            den[h] += ex;
            acc[h].x += ex * v4[h].x; acc[h].y += ex * v4[h].y;
            acc[h].z += ex * v4[h].z; acc[h].w += ex * v4[h].w;
        }
    }

    float4 o = make_float4(0.f, 0.f, 0.f, 0.f);
#pragma unroll
    for (int h = 0; h < 4; h++) {
        if (den[h] > 0.f) {
            float inv = 0.25f / den[h];
            o.x += acc[h].x * inv; o.y += acc[h].y * inv;
            o.z += acc[h].z * inv; o.w += acc[h].w * inv;
        }
    }
    reinterpret_cast<float4*>(g_gout + (size_t)row * DD)[lane] = o;
}

// ---------------- bf16x3 mma.sync GEMM ----------------
// 128x64 block tile (R9 shape), BK=64, 2-stage cp.async double buffer,
// 2 CTAs/SM (smem 110592 B, 128 regs via launch_bounds).
#define LDK 72                        // 64 + 8 pad; row 144B, conflict-free ldsm
#define OA_H 0
#define OA_L (128 * LDK * 2)          // 18432
#define OW_H (2 * 128 * LDK * 2)      // 36864
#define OW_L (OW_H + 64 * LDK * 2)    // 46080
#define STG    (OW_L + 64 * LDK * 2)  // 55296 per stage
#define SM_TOT (2 * STG)              // 110592 bytes

template<bool BF16OUT, bool RELU>
__global__ __launch_bounds__(256, 2) void gemm_tc(
    const __nv_bfloat16* __restrict__ Ah, const __nv_bfloat16* __restrict__ Al,
    const __nv_bfloat16* __restrict__ Wh, const __nv_bfloat16* __restrict__ Wl,
    const float* __restrict__ bias,
    float* __restrict__ Cf, __nv_bfloat16* __restrict__ Ch,
    __nv_bfloat16* __restrict__ Cl,
    int M, int Nc, int K)
{
    extern __shared__ char smem[];
    const uint32_t smb = (uint32_t)__cvta_generic_to_shared(smem);

    const int tid  = threadIdx.x;
    const int lane = tid & 31;
    const int w    = tid >> 5;
    const int wm   = w & 3;
    const int wn   = w >> 2;
    const int bm   = blockIdx.y * 128;
    const int bn   = blockIdx.x * 64;

    const int lrow = lane & 7;
    const int quad = lane >> 3;
    const int a_roff = lrow + ((quad & 1) << 3);
    const int a_coff = (quad >> 1) << 3;
    const int b_roff = lrow + ((quad >> 1) << 3);
    const int b_coff = (quad & 1) << 3;

    float acc[2][4][4];
#pragma unroll
    for (int i = 0; i < 2; i++)
#pragma unroll
        for (int j = 0; j < 4; j++)
#pragma unroll
            for (int t = 0; t < 4; t++) acc[i][j][t] = 0.f;

    // staging coords: i = tid + it*256; row = i>>3 (0..127), c8 = i&7 (8 elems)
    const int s_row = tid >> 3;
    const int s_c8  = (tid & 7) * 8;

    auto stage_fn = [&](int s, int k0) {
        uint32_t base = smb + s * STG;
#pragma unroll
        for (int it = 0; it < 4; it++) {
            int row = s_row + it * 32;
            uint32_t d = base + (row * LDK + s_c8) * 2;
            int ga = bm + row; if (ga >= M) ga = M - 1;
            size_t aoff = (size_t)ga * K + k0 + s_c8;
            cp16(d + OA_H, Ah + aoff);
            cp16(d + OA_L, Al + aoff);
            if (it < 2) {
                int wr = row + (it & 1) * 0;  // rows 0..63 over it=0,1
                size_t woff = (size_t)(bn + wr) * K + k0 + s_c8;
                if (it == 0 || wr + 32 < 64) {}
                // handled below instead
            }
        }
        // W rows 0..63: i = tid + it*256, it=0..1
#pragma unroll
        for (int it = 0; it < 2; it++) {
            int row = s_row + it * 32;
            uint32_t d = base + (row * LDK + s_c8) * 2;
            size_t woff = (size_t)(bn + row) * K + k0 + s_c8;
            cp16(d + OW_H, Wh + woff);
            cp16(d + OW_L, Wl + woff);
        }
        asm volatile("cp.async.commit_group;");
    };

    const int nCh = K >> 6;
    stage_fn(0, 0);

    for (int c = 0; c < nCh; c++) {
        if (c + 1 < nCh) {
            stage_fn((c + 1) & 1, (c + 1) << 6);
            asm volatile("cp.async.wait_group 1;");
        } else {
            asm volatile("cp.async.wait_group 0;");
        }
        __syncthreads();

        uint32_t base = smb + (c & 1) * STG;
#pragma unroll
        for (int ks = 0; ks < 64; ks += 16) {
            uint32_t ahf[2][4], alf[2][4], bhf[4][2], blf[4][2];
#pragma unroll
            for (int i = 0; i < 2; i++) {
                uint32_t off = (uint32_t)(((wm * 32 + i * 16 + a_roff) * LDK
                                           + ks + a_coff) * 2);
                ldsm_x4(ahf[i][0], ahf[i][1], ahf[i][2], ahf[i][3],
                        base + OA_H + off);
                ldsm_x4(alf[i][0], alf[i][1], alf[i][2], alf[i][3],
                        base + OA_L + off);
            }
#pragma unroll
            for (int jp = 0; jp < 2; jp++) {
                uint32_t off = (uint32_t)(((wn * 32 + jp * 16 + b_roff) * LDK
                                           + ks + b_coff) * 2);
                ldsm_x4(bhf[2 * jp][0], bhf[2 * jp][1],
                        bhf[2 * jp + 1][0], bhf[2 * jp + 1][1],
                        base + OW_H + off);
                ldsm_x4(blf[2 * jp][0], blf[2 * jp][1],
                        blf[2 * jp + 1][0], blf[2 * jp + 1][1],
                        base + OW_L + off);
            }
#pragma unroll
            for (int i = 0; i < 2; i++)
#pragma unroll
                for (int j = 0; j < 4; j++) {
                    mma_bf16(acc[i][j], ahf[i], bhf[j]);
                    mma_bf16(acc[i][j], ahf[i], blf[j]);
                    mma_bf16(acc[i][j], alf[i], bhf[j]);
                }
        }
        __syncthreads();   // buffer consumed before it is re-staged
    }

    const int qr = lane >> 2;
    const int kq = (lane & 3) * 2;
#pragma unroll
    for (int i = 0; i < 2; i++) {
        int r0 = bm + wm * 32 + i * 16 + qr;
#pragma unroll
        for (int j = 0; j < 4; j++) {
            int c = bn + wn * 32 + j * 8 + kq;
            float b0 = bias[c], b1 = bias[c + 1];
            float v0 = acc[i][j][0] + b0, v1 = acc[i][j][1] + b1;
            float v2 = acc[i][j][2] + b0, v3 = acc[i][j][3] + b1;
            if (RELU) {
                v0 = fmaxf(v0, 0.f); v1 = fmaxf(v1, 0.f);
                v2 = fmaxf(v2, 0.f); v3 = fmaxf(v3, 0.f);
            }
            if (!BF16OUT) {
                if (r0 < M)
                    *reinterpret_cast<float2*>(Cf + (size_t)r0 * Nc + c) =
                        make_float2(v0, v1);
                if (r0 + 8 < M)
                    *reinterpret_cast<float2*>(Cf + (size_t)(r0 + 8) * Nc + c) =
                        make_float2(v2, v3);
            } else {
                __nv_bfloat162 hh2, ll2;
                if (r0 < M) {
                    split2(v0, v1, hh2, ll2);
                    *reinterpret_cast<__nv_bfloat162*>(Ch + (size_t)r0 * Nc + c) = hh2;
                    *reinterpret_cast<__nv_bfloat162*>(Cl + (size_t)r0 * Nc + c) = ll2;
                }
                if (r0 + 8 < M) {
                    split2(v2, v3, hh2, ll2);
                    *reinterpret_cast<__nv_bfloat162*>(Ch + (size_t)(r0 + 8) * Nc + c) = hh2;
                    *reinterpret_cast<__nv_bfloat162*>(Cl + (size_t)(r0 + 8) * Nc + c) = ll2;
                }
            }
        }
    }
}

// ---------------- layernorm ----------------
__device__ __forceinline__ float4 ln_core(float4 vv, int lane,
                                          const float* __restrict__ g,
                                          const float* __restrict__ b) {
    float sum = vv.x + vv.y + vv.z + vv.w;
    float sq = vv.x * vv.x + vv.y * vv.y + vv.z * vv.z + vv.w * vv.w;
#pragma unroll
    for (int o = 16; o > 0; o >>= 1) {
        sum += __shfl_xor_sync(0xffffffffu, sum, o);
        sq  += __shfl_xor_sync(0xffffffffu, sq, o);
    }
    float mu = sum * (1.f / 128.f);
    float var = sq * (1.f / 128.f) - mu * mu;
    float rstd = rsqrtf(var + 1e-5f);
    float4 gv = reinterpret_cast<const float4*>(g)[lane];
    float4 bv = reinterpret_cast<const float4*>(b)[lane];
    float4 o;
    o.x = (vv.x - mu) * rstd * gv.x + bv.x;
    o.y = (vv.y - mu) * rstd * gv.y + bv.y;
    o.z = (vv.z - mu) * rstd * gv.z + bv.z;
    o.w = (vv.w - mu) * rstd * gv.w + bv.w;
    return o;
}

__global__ void ln1_kernel(const float* __restrict__ x,
                           const float* __restrict__ g, const float* __restrict__ b) {
    int row = (blockIdx.x * blockDim.x + threadIdx.x) >> 5;
    int lane = threadIdx.x & 31;
    if (row >= NN) return;
    float4 xv = reinterpret_cast<const float4*>(x + (size_t)row * DD)[lane];
    float4 sv = reinterpret_cast<const float4*>(g_qkvs + (size_t)row * NFUSE + 1536)[lane];
    float4 gv = reinterpret_cast<const float4*>(g_gout + (size_t)row * DD)[lane];
    float4 vv = make_float4(xv.x + sv.x + gv.x, xv.y + sv.y + gv.y,
                            xv.z + sv.z + gv.z, xv.w + sv.w + gv.w);
    float4 o = ln_core(vv, lane, g, b);
    reinterpret_cast<float4*>(g_x1 + (size_t)row * DD)[lane] = o;
}

__global__ void ln_add_kernel(const float* __restrict__ a, const float* __restrict__ bb,
                              const float* __restrict__ g, const float* __restrict__ beta,
                              float* __restrict__ out,
                              __nv_bfloat16* __restrict__ oh,
                              __nv_bfloat16* __restrict__ ol) {
    int row = (blockIdx.x * blockDim.x + threadIdx.x) >> 5;
    int lane = threadIdx.x & 31;
    if (row >= NN) return;
    float4 av = reinterpret_cast<const float4*>(a + (size_t)row * DD)[lane];
    float4 bv = reinterpret_cast<const float4*>(bb + (size_t)row * DD)[lane];
    float4 vv = make_float4(av.x + bv.x, av.y + bv.y, av.z + bv.z, av.w + bv.w);
    float4 o = ln_core(vv, lane, g, beta);
    reinterpret_cast<float4*>(out + (size_t)row * DD)[lane] = o;
    if (oh) {
        __nv_bfloat162 h01, l01, h23, l23;
        split2(o.x, o.y, h01, l01);
        split2(o.z, o.w, h23, l23);
        size_t base = (size_t)row * DD + lane * 4;
        *reinterpret_cast<__nv_bfloat162*>(oh + base)     = h01;
        *reinterpret_cast<__nv_bfloat162*>(oh + base + 2) = h23;
        *reinterpret_cast<__nv_bfloat162*>(ol + base)     = l01;
        *reinterpret_cast<__nv_bfloat162*>(ol + base + 2) = l23;
    }
}

// ---------------- launch ----------------
static void* sym(const void* s) { void* p = nullptr; cudaGetSymbolAddress(&p, s); return p; }

extern "C" void kernel_launch(void* const* d_in, const int* in_sizes, int n_in,
                              void* d_out, int out_size)
{
    const float* x    = (const float*)d_in[0];
    const float* te   = (const float*)d_in[1];
    const float* gq_w = (const float*)d_in[2];  const float* gq_b = (const float*)d_in[3];
    const float* gk_w = (const float*)d_in[4];  const float* gk_b = (const float*)d_in[5];
    const float* gv_w = (const float*)d_in[6];  const float* gv_b = (const float*)d_in[7];
    const float* gs_w = (const float*)d_in[8];  const float* gs_b = (const float*)d_in[9];
    // mha_wq/bq, mha_wk/bk dead: softmax over one kv position is exactly 1.
    const float* wv   = (const float*)d_in[14]; const float* bv   = (const float*)d_in[15];
    const float* wo   = (const float*)d_in[16]; const float* bo   = (const float*)d_in[17];
    const float* w1   = (const float*)d_in[18]; const float* b1   = (const float*)d_in[19];
    const float* w2   = (const float*)d_in[20]; const float* b2   = (const float*)d_in[21];
    const float* ln1g = (const float*)d_in[22]; const float* ln1b = (const float*)d_in[23];
    const float* ln2g = (const float*)d_in[24]; const float* ln2b = (const float*)d_in[25];
    const float* ln3g = (const float*)d_in[26]; const float* ln3b = (const float*)d_in[27];
    const int*   ei   = (const int*)d_in[28];
    float* out = (float*)d_out;

    float* qkvs_p = (float*)sym(g_qkvs);
    float* x1_p   = (float*)sym(g_x1);
    float* tout_p = (float*)sym(g_tout);
    float* x2_p   = (float*)sym(g_x2);
    float* ffn_p  = (float*)sym(g_ffn);
    float* bf_p   = (float*)sym(g_bias_f);

    __nv_bfloat16* xh  = (__nv_bfloat16*)sym(g_xh);  __nv_bfloat16* xl  = (__nv_bfloat16*)sym(g_xl);
    __nv_bfloat16* teh = (__nv_bfloat16*)sym(g_teh); __nv_bfloat16* tel = (__nv_bfloat16*)sym(g_tel);
    __nv_bfloat16* tvh = (__nv_bfloat16*)sym(g_tvh); __nv_bfloat16* tvl = (__nv_bfloat16*)sym(g_tvl);
    __nv_bfloat16* x2h = (__nv_bfloat16*)sym(g_x2h); __nv_bfloat16* x2l = (__nv_bfloat16*)sym(g_x2l);
    __nv_bfloat16* hh  = (__nv_bfloat16*)sym(g_hh);  __nv_bfloat16* hl  = (__nv_bfloat16*)sym(g_hl);
    __nv_bfloat16* wfh = (__nv_bfloat16*)sym(g_wfh); __nv_bfloat16* wfl = (__nv_bfloat16*)sym(g_wfl);
    __nv_bfloat16* mvh = (__nv_bfloat16*)sym(g_mvh); __nv_bfloat16* mvl = (__nv_bfloat16*)sym(g_mvl);
    __nv_bfloat16* moh = (__nv_bfloat16*)sym(g_moh); __nv_bfloat16* mol = (__nv_bfloat16*)sym(g_mol);
    __nv_bfloat16* w1h = (__nv_bfloat16*)sym(g_w1h); __nv_bfloat16* w1l = (__nv_bfloat16*)sym(g_w1l);
    __nv_bfloat16* w2h = (__nv_bfloat16*)sym(g_w2h); __nv_bfloat16* w2l = (__nv_bfloat16*)sym(g_w2l);

    cudaFuncSetAttribute(gemm_tc<false, false>,
                         cudaFuncAttributeMaxDynamicSharedMemorySize, SM_TOT);
    cudaFuncSetAttribute(gemm_tc<true, false>,
                         cudaFuncAttributeMaxDynamicSharedMemorySize, SM_TOT);
    cudaFuncSetAttribute(gemm_tc<true, true>,
                         cudaFuncAttributeMaxDynamicSharedMemorySize, SM_TOT);

    const int MB = (NN + 127) / 128;       // 157
    const int NSCAN = (NN + 1023) / 1024;  // 20

    bias_concat<<<(NFUSE + 255) / 256, 256>>>(gq_b, gk_b, gv_b, gs_b);

    // CSR build (depends only on ei)
    deg_zero_kernel<<<(NN + 255) / 256, 256>>>();
    hist_kernel<<<(EE + 255) / 256, 256>>>(ei);
    scanA_kernel<<<NSCAN, 1024>>>();
    scanB_kernel<<<1, 32>>>(NSCAN);
    scanC_kernel<<<(NN + 255) / 256, 256>>>();
    fill_kernel<<<(EE + 255) / 256, 256>>>(ei);

    CJs jobs;
    jobs.j[0] = {x,    xh,  xl,  NN * DD / 4};
    jobs.j[1] = {te,   teh, tel, NN * DD / 4};
    jobs.j[2] = {gq_w, wfh,               wfl,               512 * 128 / 4};
    jobs.j[3] = {gk_w, wfh + 512 * 128,   wfl + 512 * 128,   512 * 128 / 4};
    jobs.j[4] = {gv_w, wfh + 1024 * 128,  wfl + 1024 * 128,  512 * 128 / 4};
    jobs.j[5] = {gs_w, wfh + 1536 * 128,  wfl + 1536 * 128,  128 * 128 / 4};
    jobs.j[6] = {wv,   mvh, mvl, 128 * 128 / 4};
    jobs.j[7] = {wo,   moh, mol, 128 * 128 / 4};
    jobs.j[8] = {w1,   w1h, w1l, 512 * 128 / 4};
    jobs.j[9] = {w2,   w2h, w2l, 128 * 512 / 4};
    conv_batch<<<dim3(96, 10), 256>>>(jobs);

    // fused q|k|v|skip projection: [NN,1664] = x @ [1664,128]^T + bias
    gemm_tc<false, false><<<dim3(NFUSE / 64, MB), 256, SM_TOT>>>(
        xh, xl, wfh, wfl, bf_p, qkvs_p, nullptr, nullptr, NN, NFUSE, 128);
    // temporal branch
    gemm_tc<true, false><<<dim3(2, MB), 256, SM_TOT>>>(
        teh, tel, mvh, mvl, bv, nullptr, tvh, tvl, NN, 128, 128);
    gemm_tc<false, false><<<dim3(2, MB), 256, SM_TOT>>>(
        tvh, tvl, moh, mol, bo, tout_p, nullptr, nullptr, NN, 128, 128);

    // graph attention: warp-per-dst, register accumulation, no atomics
    edge_dst_kernel<<<(NN + 7) / 8, 256>>>();

    ln1_kernel<<<(NN + 7) / 8, 256>>>(x, ln1g, ln1b);
    ln_add_kernel<<<(NN + 7) / 8, 256>>>(x1_p, tout_p, ln2g, ln2b, x2_p, x2h, x2l);
    // FFN
    gemm_tc<true, true><<<dim3(8, MB), 256, SM_TOT>>>(
        x2h, x2l, w1h, w1l, b1, nullptr, hh, hl, NN, 512, 128);
    gemm_tc<false, false><<<dim3(2, MB), 256, SM_TOT>>>(
        hh, hl, w2h, w2l, b2, ffn_p, nullptr, nullptr, NN, 128, 512);
    ln_add_kernel<<<(NN + 7) / 8, 256>>>(x2_p, ffn_p, ln3g, ln3b, out, nullptr, nullptr);
}

// round 13
// speedup vs baseline: 1.3381x; 1.0380x over previous
#include <cuda_runtime.h>
#include <cuda_bf16.h>
#include <math.h>
#include <math_constants.h>
#include <stdint.h>

#define NN 20000
#define EE 160000
#define DD 128
#define NFUSE 1664   // 512(q)+512(k)+512(v)+128(skip)

// ---------------- scratch (static device globals; no allocation) ----------------
__device__ float g_qkvs[NN * NFUSE];   // fused q|k|v|skip, row stride 1664
__device__ float g_gout[NN * DD];      // normalized head-mean graph attention output
__device__ float g_tout[NN * DD];
__device__ float g_x2[NN * DD];
__device__ float g_ffn[NN * DD];
__device__ float g_bias_f[NFUSE];
__device__ float g_wc[128 * 128];      // composed temporal weight Wo@Wv
__device__ float g_bc[128];            // composed temporal bias Wo@bv+bo
// CSR scratch
__device__ int g_deg[NN];
__device__ int g_rowptr[NN + 1];
__device__ int g_cursor[NN];
__device__ int g_blocksum[32];
__device__ int g_ssrc[EE];

// bf16 hi/lo operand buffers
__device__ __nv_bfloat16 g_xh[NN * DD],  g_xl[NN * DD];
__device__ __nv_bfloat16 g_teh[NN * DD], g_tel[NN * DD];
__device__ __nv_bfloat16 g_x2h[NN * DD], g_x2l[NN * DD];
__device__ __nv_bfloat16 g_hh[NN * 512], g_hl[NN * 512];
__device__ __nv_bfloat16 g_wfh[NFUSE * 128], g_wfl[NFUSE * 128];
__device__ __nv_bfloat16 g_wch[128 * 128], g_wcl[128 * 128];
__device__ __nv_bfloat16 g_w1h[512 * 128], g_w1l[512 * 128];
__device__ __nv_bfloat16 g_w2h[128 * 512], g_w2l[128 * 512];

// ---------------- helpers ----------------
__device__ __forceinline__ void split2(float x, float y,
                                       __nv_bfloat162& h, __nv_bfloat162& l) {
    __nv_bfloat16 hx = __float2bfloat16(x);
    __nv_bfloat16 hy = __float2bfloat16(y);
    __nv_bfloat16 lx = __float2bfloat16(x - __bfloat162float(hx));
    __nv_bfloat16 ly = __float2bfloat16(y - __bfloat162float(hy));
    h = __halves2bfloat162(hx, hy);
    l = __halves2bfloat162(lx, ly);
}

__device__ __forceinline__ void mma_bf16(float* c, const uint32_t* a, const uint32_t* b) {
    asm volatile(
        "mma.sync.aligned.m16n8k16.row.col.f32.bf16.bf16.f32 "
        "{%0,%1,%2,%3}, {%4,%5,%6,%7}, {%8,%9}, {%0,%1,%2,%3};"
        : "+f"(c[0]), "+f"(c[1]), "+f"(c[2]), "+f"(c[3])
        : "r"(a[0]), "r"(a[1]), "r"(a[2]), "r"(a[3]), "r"(b[0]), "r"(b[1]));
}

__device__ __forceinline__ void ldsm_x4(uint32_t& r0, uint32_t& r1, uint32_t& r2,
                                        uint32_t& r3, uint32_t addr) {
    asm volatile("ldmatrix.sync.aligned.m8n8.x4.shared.b16 {%0,%1,%2,%3}, [%4];"
                 : "=r"(r0), "=r"(r1), "=r"(r2), "=r"(r3) : "r"(addr));
}

__device__ __forceinline__ void cp16(uint32_t dst, const void* src) {
    asm volatile("cp.async.cg.shared.global [%0], [%1], 16;" :: "r"(dst), "l"(src));
}

// ---------------- setup: deg=0 + concat graph biases ----------------
__global__ void setup_kernel(const float* a, const float* b,
                             const float* c, const float* d) {
    int i = blockIdx.x * blockDim.x + threadIdx.x;
    if (i < NN) g_deg[i] = 0;
    if (i < 512) g_bias_f[i] = a[i];
    else if (i < 1024) g_bias_f[i] = b[i - 512];
    else if (i < 1536) g_bias_f[i] = c[i - 1024];
    else if (i < NFUSE) g_bias_f[i] = d[i - 1536];
}

// ---------------- temporal weight composition: Wc = Wo@Wv, bc = Wo@bv + bo ----------------
__global__ void compose_temporal(const float* __restrict__ wo,
                                 const float* __restrict__ wv,
                                 const float* __restrict__ bv,
                                 const float* __restrict__ bo) {
    int i = blockIdx.x;      // output row (0..127)
    int j = threadIdx.x;     // column (0..127)
    __shared__ float wo_s[128];
    __shared__ float bs[4];
    wo_s[j] = wo[i * 128 + j];
    __syncthreads();
    float sum = 0.f;
#pragma unroll 8
    for (int k = 0; k < 128; k++) sum += wo_s[k] * wv[k * 128 + j];
    g_wc[i * 128 + j] = sum;
    float bb = wo_s[j] * bv[j];
#pragma unroll
    for (int o = 16; o > 0; o >>= 1) bb += __shfl_xor_sync(0xffffffffu, bb, o);
    if ((j & 31) == 0) bs[j >> 5] = bb;
    __syncthreads();
    if (j == 0) g_bc[i] = bs[0] + bs[1] + bs[2] + bs[3] + bo[i];
}

// ---------------- batched fp32 -> bf16 hi/lo conversion ----------------
struct CJ { const float* s; __nv_bfloat16* h; __nv_bfloat16* l; int n4; };
struct CJs { CJ j[9]; };

__global__ void conv_batch(CJs jobs) {
    CJ job = jobs.j[blockIdx.y];
    int stride = gridDim.x * blockDim.x;
    for (int i = blockIdx.x * blockDim.x + threadIdx.x; i < job.n4; i += stride) {
        float4 v = reinterpret_cast<const float4*>(job.s)[i];
        __nv_bfloat162 h01, l01, h23, l23;
        split2(v.x, v.y, h01, l01);
        split2(v.z, v.w, h23, l23);
        reinterpret_cast<__nv_bfloat162*>(job.h)[2 * i]     = h01;
        reinterpret_cast<__nv_bfloat162*>(job.h)[2 * i + 1] = h23;
        reinterpret_cast<__nv_bfloat162*>(job.l)[2 * i]     = l01;
        reinterpret_cast<__nv_bfloat162*>(job.l)[2 * i + 1] = l23;
    }
}

// ---------------- CSR build ----------------
__global__ void hist_kernel(const int* __restrict__ ei) {
    int e = blockIdx.x * blockDim.x + threadIdx.x;
    if (e < EE) atomicAdd(&g_deg[ei[EE + e]], 1);
}
__global__ void scanA_kernel() {
    int t = threadIdx.x, b = blockIdx.x;
    int idx = b * 1024 + t;
    int v = (idx < NN) ? g_deg[idx] : 0;
    int lane = t & 31, wid = t >> 5;
    int x = v;
#pragma unroll
    for (int o = 1; o < 32; o <<= 1) {
        int y = __shfl_up_sync(0xffffffffu, x, o);
        if (lane >= o) x += y;
    }
    __shared__ int wsum[32];
    if (lane == 31) wsum[wid] = x;
    __syncthreads();
    if (wid == 0) {
        int w = wsum[lane];
#pragma unroll
        for (int o = 1; o < 32; o <<= 1) {
            int y = __shfl_up_sync(0xffffffffu, w, o);
            if (lane >= o) w += y;
        }
        wsum[lane] = w;
    }
    __syncthreads();
    int incl = x + (wid > 0 ? wsum[wid - 1] : 0);
    if (idx < NN) g_rowptr[idx] = incl - v;
    if (t == 1023) g_blocksum[b] = incl;
}
// scanC with inlined cross-block prefix (blocks of 256 never straddle 1024 chunks)
__global__ void scanC_kernel() {
    __shared__ int base_s;
    if (threadIdx.x == 0) {
        int nb = blockIdx.x >> 2;
        int s = 0;
        for (int k = 0; k < nb; k++) s += g_blocksum[k];
        base_s = s;
    }
    __syncthreads();
    int i = blockIdx.x * 256 + threadIdx.x;
    if (i < NN) {
        int r = g_rowptr[i] + base_s;
        g_rowptr[i] = r;
        g_cursor[i] = r;
    }
    if (i == 0) g_rowptr[NN] = EE;
}
__global__ void fill_kernel(const int* __restrict__ ei) {
    int e = blockIdx.x * blockDim.x + threadIdx.x;
    if (e >= EE) return;
    int dst = ei[EE + e];
    int pos = atomicAdd(&g_cursor[dst], 1);
    g_ssrc[pos] = ei[e];
}

// ---------------- per-dst edge aggregation (no atomics, src-index prefetch) ----------------
__global__ void edge_dst_kernel() {
    int row = (blockIdx.x * blockDim.x + threadIdx.x) >> 5;
    int lane = threadIdx.x & 31;
    if (row >= NN) return;
    const float4* qr = reinterpret_cast<const float4*>(g_qkvs + (size_t)row * NFUSE);
    float4 q4[4];
#pragma unroll
    for (int h = 0; h < 4; h++) q4[h] = qr[h * 32 + lane];

    float4 acc[4];
    float den[4];
#pragma unroll
    for (int h = 0; h < 4; h++) {
        acc[h] = make_float4(0.f, 0.f, 0.f, 0.f);
        den[h] = 0.f;
    }

    int p0 = g_rowptr[row], p1 = g_rowptr[row + 1];
    int nsrc = (p0 < p1) ? g_ssrc[p0] : 0;
    for (int p = p0; p < p1; p++) {
        int src = nsrc;
        if (p + 1 < p1) nsrc = g_ssrc[p + 1];   // prefetch next index
        const float4* kr = reinterpret_cast<const float4*>(
            g_qkvs + (size_t)src * NFUSE + 512);
        const float4* vr = kr + 128;
        float4 k4[4], v4[4];
#pragma unroll
        for (int h = 0; h < 4; h++) { k4[h] = kr[h * 32 + lane]; v4[h] = vr[h * 32 + lane]; }
        float s[4];
#pragma unroll
        for (int h = 0; h < 4; h++)
            s[h] = q4[h].x * k4[h].x + q4[h].y * k4[h].y
                 + q4[h].z * k4[h].z + q4[h].w * k4[h].w;
#pragma unroll
        for (int h = 0; h < 4; h++)
#pragma unroll
            for (int o = 16; o > 0; o >>= 1)
                s[h] += __shfl_xor_sync(0xffffffffu, s[h], o);
#pragma unroll
        for (int h = 0; h < 4; h++) {
            float ex = expf(s[h] * 0.0883883476483184f);  // 1/sqrt(128)
            den[h] += ex;
            acc[h].x += ex * v4[h].x; acc[h].y += ex * v4[h].y;
            acc[h].z += ex * v4[h].z; acc[h].w += ex * v4[h].w;
        }
    }

    float4 o = make_float4(0.f, 0.f, 0.f, 0.f);
#pragma unroll
    for (int h = 0; h < 4; h++) {
        if (den[h] > 0.f) {
            float inv = 0.25f / den[h];
            o.x += acc[h].x * inv; o.y += acc[h].y * inv;
            o.z += acc[h].z * inv; o.w += acc[h].w * inv;
        }
    }
    reinterpret_cast<float4*>(g_gout + (size_t)row * DD)[lane] = o;
}

// ---------------- bf16x3 mma.sync GEMM ----------------
// 128x64 block tile, BK=64, 2-stage cp.async double buffer, 2 CTAs/SM.
#define LDK 72
#define OA_H 0
#define OA_L (128 * LDK * 2)
#define OW_H (2 * 128 * LDK * 2)
#define OW_L (OW_H + 64 * LDK * 2)
#define STG    (OW_L + 64 * LDK * 2)  // 55296 per stage
#define SM_TOT (2 * STG)              // 110592 bytes

template<bool BF16OUT, bool RELU>
__global__ __launch_bounds__(256, 2) void gemm_tc(
    const __nv_bfloat16* __restrict__ Ah, const __nv_bfloat16* __restrict__ Al,
    const __nv_bfloat16* __restrict__ Wh, const __nv_bfloat16* __restrict__ Wl,
    const float* __restrict__ bias,
    float* __restrict__ Cf, __nv_bfloat16* __restrict__ Ch,
    __nv_bfloat16* __restrict__ Cl,
    int M, int Nc, int K)
{
    extern __shared__ char smem[];
    const uint32_t smb = (uint32_t)__cvta_generic_to_shared(smem);

    const int tid  = threadIdx.x;
    const int lane = tid & 31;
    const int w    = tid >> 5;
    const int wm   = w & 3;
    const int wn   = w >> 2;
    const int bm   = blockIdx.y * 128;
    const int bn   = blockIdx.x * 64;

    const int lrow = lane & 7;
    const int quad = lane >> 3;
    const int a_roff = lrow + ((quad & 1) << 3);
    const int a_coff = (quad >> 1) << 3;
    const int b_roff = lrow + ((quad >> 1) << 3);
    const int b_coff = (quad & 1) << 3;

    float acc[2][4][4];
#pragma unroll
    for (int i = 0; i < 2; i++)
#pragma unroll
        for (int j = 0; j < 4; j++)
#pragma unroll
            for (int t = 0; t < 4; t++) acc[i][j][t] = 0.f;

    const int s_row = tid >> 3;
    const int s_c8  = (tid & 7) * 8;

    auto stage_fn = [&](int s, int k0) {
        uint32_t base = smb + s * STG;
#pragma unroll
        for (int it = 0; it < 4; it++) {
            int row = s_row + it * 32;
            uint32_t d = base + (row * LDK + s_c8) * 2;
            int ga = bm + row; if (ga >= M) ga = M - 1;
            size_t aoff = (size_t)ga * K + k0 + s_c8;
            cp16(d + OA_H, Ah + aoff);
            cp16(d + OA_L, Al + aoff);
        }
#pragma unroll
        for (int it = 0; it < 2; it++) {
            int row = s_row + it * 32;
            uint32_t d = base + (row * LDK + s_c8) * 2;
            size_t woff = (size_t)(bn + row) * K + k0 + s_c8;
            cp16(d + OW_H, Wh + woff);
            cp16(d + OW_L, Wl + woff);
        }
        asm volatile("cp.async.commit_group;");
    };

    const int nCh = K >> 6;
    stage_fn(0, 0);

    for (int c = 0; c < nCh; c++) {
        if (c + 1 < nCh) {
            stage_fn((c + 1) & 1, (c + 1) << 6);
            asm volatile("cp.async.wait_group 1;");
        } else {
            asm volatile("cp.async.wait_group 0;");
        }
        __syncthreads();

        uint32_t base = smb + (c & 1) * STG;
#pragma unroll
        for (int ks = 0; ks < 64; ks += 16) {
            uint32_t ahf[2][4], alf[2][4], bhf[4][2], blf[4][2];
#pragma unroll
            for (int i = 0; i < 2; i++) {
                uint32_t off = (uint32_t)(((wm * 32 + i * 16 + a_roff) * LDK
                                           + ks + a_coff) * 2);
                ldsm_x4(ahf[i][0], ahf[i][1], ahf[i][2], ahf[i][3],
                        base + OA_H + off);
                ldsm_x4(alf[i][0], alf[i][1], alf[i][2], alf[i][3],
                        base + OA_L + off);
            }
#pragma unroll
            for (int jp = 0; jp < 2; jp++) {
                uint32_t off = (uint32_t)(((wn * 32 + jp * 16 + b_roff) * LDK
                                           + ks + b_coff) * 2);
                ldsm_x4(bhf[2 * jp][0], bhf[2 * jp][1],
                        bhf[2 * jp + 1][0], bhf[2 * jp + 1][1],
                        base + OW_H + off);
                ldsm_x4(blf[2 * jp][0], blf[2 * jp][1],
                        blf[2 * jp + 1][0], blf[2 * jp + 1][1],
                        base + OW_L + off);
            }
#pragma unroll
            for (int i = 0; i < 2; i++)
#pragma unroll
                for (int j = 0; j < 4; j++) {
                    mma_bf16(acc[i][j], ahf[i], bhf[j]);
                    mma_bf16(acc[i][j], ahf[i], blf[j]);
                    mma_bf16(acc[i][j], alf[i], bhf[j]);
                }
        }
        __syncthreads();
    }

    const int qr = lane >> 2;
    const int kq = (lane & 3) * 2;
#pragma unroll
    for (int i = 0; i < 2; i++) {
        int r0 = bm + wm * 32 + i * 16 + qr;
#pragma unroll
        for (int j = 0; j < 4; j++) {
            int c = bn + wn * 32 + j * 8 + kq;
            float b0 = bias[c], b1 = bias[c + 1];
            float v0 = acc[i][j][0] + b0, v1 = acc[i][j][1] + b1;
            float v2 = acc[i][j][2] + b0, v3 = acc[i][j][3] + b1;
            if (RELU) {
                v0 = fmaxf(v0, 0.f); v1 = fmaxf(v1, 0.f);
                v2 = fmaxf(v2, 0.f); v3 = fmaxf(v3, 0.f);
            }
            if (!BF16OUT) {
                if (r0 < M)
                    *reinterpret_cast<float2*>(Cf + (size_t)r0 * Nc + c) =
                        make_float2(v0, v1);
                if (r0 + 8 < M)
                    *reinterpret_cast<float2*>(Cf + (size_t)(r0 + 8) * Nc + c) =
                        make_float2(v2, v3);
            } else {
                __nv_bfloat162 hh2, ll2;
                if (r0 < M) {
                    split2(v0, v1, hh2, ll2);
                    *reinterpret_cast<__nv_bfloat162*>(Ch + (size_t)r0 * Nc + c) = hh2;
                    *reinterpret_cast<__nv_bfloat162*>(Cl + (size_t)r0 * Nc + c) = ll2;
                }
                if (r0 + 8 < M) {
                    split2(v2, v3, hh2, ll2);
                    *reinterpret_cast<__nv_bfloat162*>(Ch + (size_t)(r0 + 8) * Nc + c) = hh2;
                    *reinterpret_cast<__nv_bfloat162*>(Cl + (size_t)(r0 + 8) * Nc + c) = ll2;
                }
            }
        }
    }
}

// ---------------- layernorm ----------------
__device__ __forceinline__ float4 ln_core(float4 vv, int lane,
                                          const float* __restrict__ g,
                                          const float* __restrict__ b) {
    float sum = vv.x + vv.y + vv.z + vv.w;
    float sq = vv.x * vv.x + vv.y * vv.y + vv.z * vv.z + vv.w * vv.w;
#pragma unroll
    for (int o = 16; o > 0; o >>= 1) {
        sum += __shfl_xor_sync(0xffffffffu, sum, o);
        sq  += __shfl_xor_sync(0xffffffffu, sq, o);
    }
    float mu = sum * (1.f / 128.f);
    float var = sq * (1.f / 128.f) - mu * mu;
    float rstd = rsqrtf(var + 1e-5f);
    float4 gv = reinterpret_cast<const float4*>(g)[lane];
    float4 bv = reinterpret_cast<const float4*>(b)[lane];
    float4 o;
    o.x = (vv.x - mu) * rstd * gv.x + bv.x;
    o.y = (vv.y - mu) * rstd * gv.y + bv.y;
    o.z = (vv.z - mu) * rstd * gv.z + bv.z;
    o.w = (vv.w - mu) * rstd * gv.w + bv.w;
    return o;
}

// x2 = LN2(LN1(x + gout + skip) + tout); also emits x2 bf16 hi/lo
__global__ void ln12_kernel(const float* __restrict__ x,
                            const float* __restrict__ ln1g, const float* __restrict__ ln1b,
                            const float* __restrict__ ln2g, const float* __restrict__ ln2b) {
    int row = (blockIdx.x * blockDim.x + threadIdx.x) >> 5;
    int lane = threadIdx.x & 31;
    if (row >= NN) return;
    float4 xv = reinterpret_cast<const float4*>(x + (size_t)row * DD)[lane];
    float4 sv = reinterpret_cast<const float4*>(g_qkvs + (size_t)row * NFUSE + 1536)[lane];
    float4 gv = reinterpret_cast<const float4*>(g_gout + (size_t)row * DD)[lane];
    float4 vv = make_float4(xv.x + sv.x + gv.x, xv.y + sv.y + gv.y,
                            xv.z + sv.z + gv.z, xv.w + sv.w + gv.w);
    float4 o1 = ln_core(vv, lane, ln1g, ln1b);
    float4 tv = reinterpret_cast<const float4*>(g_tout + (size_t)row * DD)[lane];
    float4 v2 = make_float4(o1.x + tv.x, o1.y + tv.y, o1.z + tv.z, o1.w + tv.w);
    float4 o2 = ln_core(v2, lane, ln2g, ln2b);
    reinterpret_cast<float4*>(g_x2 + (size_t)row * DD)[lane] = o2;
    __nv_bfloat162 h01, l01, h23, l23;
    split2(o2.x, o2.y, h01, l01);
    split2(o2.z, o2.w, h23, l23);
    size_t base = (size_t)row * DD + lane * 4;
    *reinterpret_cast<__nv_bfloat162*>(g_x2h + base)     = h01;
    *reinterpret_cast<__nv_bfloat162*>(g_x2h + base + 2) = h23;
    *reinterpret_cast<__nv_bfloat162*>(g_x2l + base)     = l01;
    *reinterpret_cast<__nv_bfloat162*>(g_x2l + base + 2) = l23;
}

// out = LN(a + b)
__global__ void ln_add_kernel(const float* __restrict__ a, const float* __restrict__ bb,
                              const float* __restrict__ g, const float* __restrict__ beta,
                              float* __restrict__ out) {
    int row = (blockIdx.x * blockDim.x + threadIdx.x) >> 5;
    int lane = threadIdx.x & 31;
    if (row >= NN) return;
    float4 av = reinterpret_cast<const float4*>(a + (size_t)row * DD)[lane];
    float4 bv = reinterpret_cast<const float4*>(bb + (size_t)row * DD)[lane];
    float4 vv = make_float4(av.x + bv.x, av.y + bv.y, av.z + bv.z, av.w + bv.w);
    float4 o = ln_core(vv, lane, g, beta);
    reinterpret_cast<float4*>(out + (size_t)row * DD)[lane] = o;
}

// ---------------- launch ----------------
static void* sym(const void* s) { void* p = nullptr; cudaGetSymbolAddress(&p, s); return p; }

extern "C" void kernel_launch(void* const* d_in, const int* in_sizes, int n_in,
                              void* d_out, int out_size)
{
    const float* x    = (const float*)d_in[0];
    const float* te   = (const float*)d_in[1];
    const float* gq_w = (const float*)d_in[2];  const float* gq_b = (const float*)d_in[3];
    const float* gk_w = (const float*)d_in[4];  const float* gk_b = (const float*)d_in[5];
    const float* gv_w = (const float*)d_in[6];  const float* gv_b = (const float*)d_in[7];
    const float* gs_w = (const float*)d_in[8];  const float* gs_b = (const float*)d_in[9];
    // mha_wq/bq, mha_wk/bk dead: softmax over one kv position is exactly 1.
    const float* wv   = (const float*)d_in[14]; const float* bv   = (const float*)d_in[15];
    const float* wo   = (const float*)d_in[16]; const float* bo   = (const float*)d_in[17];
    const float* w1   = (const float*)d_in[18]; const float* b1   = (const float*)d_in[19];
    const float* w2   = (const float*)d_in[20]; const float* b2   = (const float*)d_in[21];
    const float* ln1g = (const float*)d_in[22]; const float* ln1b = (const float*)d_in[23];
    const float* ln2g = (const float*)d_in[24]; const float* ln2b = (const float*)d_in[25];
    const float* ln3g = (const float*)d_in[26]; const float* ln3b = (const float*)d_in[27];
    const int*   ei   = (const int*)d_in[28];
    float* out = (float*)d_out;

    float* qkvs_p = (float*)sym(g_qkvs);
    float* tout_p = (float*)sym(g_tout);
    float* x2_p   = (float*)sym(g_x2);
    float* ffn_p  = (float*)sym(g_ffn);
    float* bf_p   = (float*)sym(g_bias_f);
    float* wc_p   = (float*)sym(g_wc);
    float* bc_p   = (float*)sym(g_bc);

    __nv_bfloat16* xh  = (__nv_bfloat16*)sym(g_xh);  __nv_bfloat16* xl  = (__nv_bfloat16*)sym(g_xl);
    __nv_bfloat16* teh = (__nv_bfloat16*)sym(g_teh); __nv_bfloat16* tel = (__nv_bfloat16*)sym(g_tel);
    __nv_bfloat16* x2h = (__nv_bfloat16*)sym(g_x2h); __nv_bfloat16* x2l = (__nv_bfloat16*)sym(g_x2l);
    __nv_bfloat16* hh  = (__nv_bfloat16*)sym(g_hh);  __nv_bfloat16* hl  = (__nv_bfloat16*)sym(g_hl);
    __nv_bfloat16* wfh = (__nv_bfloat16*)sym(g_wfh); __nv_bfloat16* wfl = (__nv_bfloat16*)sym(g_wfl);
    __nv_bfloat16* wch = (__nv_bfloat16*)sym(g_wch); __nv_bfloat16* wcl = (__nv_bfloat16*)sym(g_wcl);
    __nv_bfloat16* w1h = (__nv_bfloat16*)sym(g_w1h); __nv_bfloat16* w1l = (__nv_bfloat16*)sym(g_w1l);
    __nv_bfloat16* w2h = (__nv_bfloat16*)sym(g_w2h); __nv_bfloat16* w2l = (__nv_bfloat16*)sym(g_w2l);

    cudaFuncSetAttribute(gemm_tc<false, false>,
                         cudaFuncAttributeMaxDynamicSharedMemorySize, SM_TOT);
    cudaFuncSetAttribute(gemm_tc<true, true>,
                         cudaFuncAttributeMaxDynamicSharedMemorySize, SM_TOT);

    const int MB = (NN + 127) / 128;       // 157
    const int NSCAN = (NN + 1023) / 1024;  // 20

    // setup: deg=0 + bias concat (one launch)
    setup_kernel<<<(NN + 255) / 256, 256>>>(gq_b, gk_b, gv_b, gs_b);
    // temporal weight composition (needs only weights)
    compose_temporal<<<128, 128>>>(wo, wv, bv, bo);

    // CSR build
    hist_kernel<<<(EE + 255) / 256, 256>>>(ei);
    scanA_kernel<<<NSCAN, 1024>>>();
    scanC_kernel<<<(NN + 255) / 256, 256>>>();
    fill_kernel<<<(EE + 255) / 256, 256>>>(ei);

    CJs jobs;
    jobs.j[0] = {x,    xh,  xl,  NN * DD / 4};
    jobs.j[1] = {te,   teh, tel, NN * DD / 4};
    jobs.j[2] = {gq_w, wfh,               wfl,               512 * 128 / 4};
    jobs.j[3] = {gk_w, wfh + 512 * 128,   wfl + 512 * 128,   512 * 128 / 4};
    jobs.j[4] = {gv_w, wfh + 1024 * 128,  wfl + 1024 * 128,  512 * 128 / 4};
    jobs.j[5] = {gs_w, wfh + 1536 * 128,  wfl + 1536 * 128,  128 * 128 / 4};
    jobs.j[6] = {wc_p, wch, wcl, 128 * 128 / 4};
    jobs.j[7] = {w1,   w1h, w1l, 512 * 128 / 4};
    jobs.j[8] = {w2,   w2h, w2l, 128 * 512 / 4};
    conv_batch<<<dim3(96, 9), 256>>>(jobs);

    // fused q|k|v|skip projection
    gemm_tc<false, false><<<dim3(NFUSE / 64, MB), 256, SM_TOT>>>(
        xh, xl, wfh, wfl, bf_p, qkvs_p, nullptr, nullptr, NN, NFUSE, 128);
    // temporal (composed): tout = te @ Wc^T + bc  — single GEMM
    gemm_tc<false, false><<<dim3(2, MB), 256, SM_TOT>>>(
        teh, tel, wch, wcl, bc_p, tout_p, nullptr, nullptr, NN, 128, 128);

    // graph attention: warp-per-dst, register accumulation
    edge_dst_kernel<<<(NN + 7) / 8, 256>>>();

    // x2 = LN2(LN1(x+gout+skip) + tout), fused; emits bf16 hi/lo
    ln12_kernel<<<(NN + 7) / 8, 256>>>(x, ln1g, ln1b, ln2g, ln2b);
    // FFN
    gemm_tc<true, true><<<dim3(8, MB), 256, SM_TOT>>>(
        x2h, x2l, w1h, w1l, b1, nullptr, hh, hl, NN, 512, 128);
    gemm_tc<false, false><<<dim3(2, MB), 256, SM_TOT>>>(
        hh, hl, w2h, w2l, b2, ffn_p, nullptr, nullptr, NN, 128, 512);
    ln_add_kernel<<<(NN + 7) / 8, 256>>>(x2_p, ffn_p, ln3g, ln3b, out);
}

// round 14
// speedup vs baseline: 1.5813x; 1.1817x over previous
#include <cuda_runtime.h>
#include <cuda_fp16.h>
#include <math.h>
#include <math_constants.h>
#include <stdint.h>

#define NN 20000
#define EE 160000
#define DD 128
#define NFUSE 1664   // 512(q)+512(k)+512(v)+128(skip)

// ---------------- scratch (static device globals; no allocation) ----------------
__device__ __half g_qk[NN * 1024];     // q|k fp16, row stride 1024
__device__ float  g_vs[NN * 640];      // v|skip fp32, row stride 640
__device__ float g_gout[NN * DD];
__device__ float g_tout[NN * DD];
__device__ float g_x2[NN * DD];
__device__ float g_ffn[NN * DD];
__device__ float g_bias_f[NFUSE];
__device__ float g_wc[128 * 128];      // composed temporal weight Wo@Wv
__device__ float g_bc[128];            // composed temporal bias Wo@bv+bo
// CSR scratch
__device__ int g_deg[NN];
__device__ int g_rowptr[NN + 1];
__device__ int g_cursor[NN];
__device__ int g_blocksum[32];
__device__ int g_ssrc[EE];

// fp16 operand buffers (A-side single, W-side hi/lo)
__device__ __half g_xf[NN * DD];
__device__ __half g_tef[NN * DD];
__device__ __half g_x2f[NN * DD];
__device__ __half g_hf[NN * 512];
__device__ __half g_wfh[NFUSE * 128], g_wfl[NFUSE * 128];
__device__ __half g_wch[128 * 128],  g_wcl[128 * 128];
__device__ __half g_w1h[512 * 128],  g_w1l[512 * 128];
__device__ __half g_w2h[128 * 512],  g_w2l[128 * 512];

// ---------------- helpers ----------------
__device__ __forceinline__ void split2h(float x, float y, __half2& h, __half2& l) {
    __half hx = __float2half_rn(x), hy = __float2half_rn(y);
    __half lx = __float2half_rn(x - __half2float(hx));
    __half ly = __float2half_rn(y - __half2float(hy));
    h = __halves2half2(hx, hy);
    l = __halves2half2(lx, ly);
}

__device__ __forceinline__ void mma_f16(float* c, const uint32_t* a, const uint32_t* b) {
    asm volatile(
        "mma.sync.aligned.m16n8k16.row.col.f32.f16.f16.f32 "
        "{%0,%1,%2,%3}, {%4,%5,%6,%7}, {%8,%9}, {%0,%1,%2,%3};"
        : "+f"(c[0]), "+f"(c[1]), "+f"(c[2]), "+f"(c[3])
        : "r"(a[0]), "r"(a[1]), "r"(a[2]), "r"(a[3]), "r"(b[0]), "r"(b[1]));
}

__device__ __forceinline__ void ldsm_x4(uint32_t& r0, uint32_t& r1, uint32_t& r2,
                                        uint32_t& r3, uint32_t addr) {
    asm volatile("ldmatrix.sync.aligned.m8n8.x4.shared.b16 {%0,%1,%2,%3}, [%4];"
                 : "=r"(r0), "=r"(r1), "=r"(r2), "=r"(r3) : "r"(addr));
}

__device__ __forceinline__ void cp16(uint32_t dst, const void* src) {
    asm volatile("cp.async.cg.shared.global [%0], [%1], 16;" :: "r"(dst), "l"(src));
}

// ---------------- setup: deg=0 + concat graph biases ----------------
__global__ void setup_kernel(const float* a, const float* b,
                             const float* c, const float* d) {
    int i = blockIdx.x * blockDim.x + threadIdx.x;
    if (i < NN) g_deg[i] = 0;
    if (i < 512) g_bias_f[i] = a[i];
    else if (i < 1024) g_bias_f[i] = b[i - 512];
    else if (i < 1536) g_bias_f[i] = c[i - 1024];
    else if (i < NFUSE) g_bias_f[i] = d[i - 1536];
}

// ---------------- temporal weight composition: Wc = Wo@Wv, bc = Wo@bv + bo ----------------
__global__ void compose_temporal(const float* __restrict__ wo,
                                 const float* __restrict__ wv,
                                 const float* __restrict__ bv,
                                 const float* __restrict__ bo) {
    int i = blockIdx.x;
    int j = threadIdx.x;
    __shared__ float wo_s[128];
    __shared__ float bs[4];
    wo_s[j] = wo[i * 128 + j];
    __syncthreads();
    float sum = 0.f;
#pragma unroll 8
    for (int k = 0; k < 128; k++) sum += wo_s[k] * wv[k * 128 + j];
    g_wc[i * 128 + j] = sum;
    float bb = wo_s[j] * bv[j];
#pragma unroll
    for (int o = 16; o > 0; o >>= 1) bb += __shfl_xor_sync(0xffffffffu, bb, o);
    if ((j & 31) == 0) bs[j >> 5] = bb;
    __syncthreads();
    if (j == 0) g_bc[i] = bs[0] + bs[1] + bs[2] + bs[3] + bo[i];
}

// ---------------- conversions ----------------
// A-side: fp32 -> single fp16
struct AJ { const float* s; __half* d; int n4; };
struct AJs { AJ j[2]; };
__global__ void conv_a(AJs jobs) {
    AJ job = jobs.j[blockIdx.y];
    int stride = gridDim.x * blockDim.x;
    for (int i = blockIdx.x * blockDim.x + threadIdx.x; i < job.n4; i += stride) {
        float4 v = reinterpret_cast<const float4*>(job.s)[i];
        __half2 a = __floats2half2_rn(v.x, v.y);
        __half2 b = __floats2half2_rn(v.z, v.w);
        reinterpret_cast<__half2*>(job.d)[2 * i]     = a;
        reinterpret_cast<__half2*>(job.d)[2 * i + 1] = b;
    }
}
// W-side: fp32 -> fp16 hi/lo
struct WJ { const float* s; __half* h; __half* l; int n4; };
struct WJs { WJ j[7]; };
__global__ void conv_w(WJs jobs) {
    WJ job = jobs.j[blockIdx.y];
    int stride = gridDim.x * blockDim.x;
    for (int i = blockIdx.x * blockDim.x + threadIdx.x; i < job.n4; i += stride) {
        float4 v = reinterpret_cast<const float4*>(job.s)[i];
        __half2 h01, l01, h23, l23;
        split2h(v.x, v.y, h01, l01);
        split2h(v.z, v.w, h23, l23);
        reinterpret_cast<__half2*>(job.h)[2 * i]     = h01;
        reinterpret_cast<__half2*>(job.h)[2 * i + 1] = h23;
        reinterpret_cast<__half2*>(job.l)[2 * i]     = l01;
        reinterpret_cast<__half2*>(job.l)[2 * i + 1] = l23;
    }
}

// ---------------- CSR build ----------------
__global__ void hist_kernel(const int* __restrict__ ei) {
    int e = blockIdx.x * blockDim.x + threadIdx.x;
    if (e < EE) atomicAdd(&g_deg[ei[EE + e]], 1);
}
__global__ void scanA_kernel() {
    int t = threadIdx.x, b = blockIdx.x;
    int idx = b * 1024 + t;
    int v = (idx < NN) ? g_deg[idx] : 0;
    int lane = t & 31, wid = t >> 5;
    int x = v;
#pragma unroll
    for (int o = 1; o < 32; o <<= 1) {
        int y = __shfl_up_sync(0xffffffffu, x, o);
        if (lane >= o) x += y;
    }
    __shared__ int wsum[32];
    if (lane == 31) wsum[wid] = x;
    __syncthreads();
    if (wid == 0) {
        int w = wsum[lane];
#pragma unroll
        for (int o = 1; o < 32; o <<= 1) {
            int y = __shfl_up_sync(0xffffffffu, w, o);
            if (lane >= o) w += y;
        }
        wsum[lane] = w;
    }
    __syncthreads();
    int incl = x + (wid > 0 ? wsum[wid - 1] : 0);
    if (idx < NN) g_rowptr[idx] = incl - v;
    if (t == 1023) g_blocksum[b] = incl;
}
__global__ void scanC_kernel() {
    __shared__ int base_s;
    if (threadIdx.x == 0) {
        int nb = blockIdx.x >> 2;
        int s = 0;
        for (int k = 0; k < nb; k++) s += g_blocksum[k];
        base_s = s;
    }
    __syncthreads();
    int i = blockIdx.x * 256 + threadIdx.x;
    if (i < NN) {
        int r = g_rowptr[i] + base_s;
        g_rowptr[i] = r;
        g_cursor[i] = r;
    }
    if (i == 0) g_rowptr[NN] = EE;
}
__global__ void fill_kernel(const int* __restrict__ ei) {
    int e = blockIdx.x * blockDim.x + threadIdx.x;
    if (e >= EE) return;
    int dst = ei[EE + e];
    int pos = atomicAdd(&g_cursor[dst], 1);
    g_ssrc[pos] = ei[e];
}

// ---------------- per-dst edge aggregation ----------------
// q/k fp16 (safe: alpha ~ N(0,8e-4), softmax weight perturbation ~1e-6 abs),
// v fp32. Warp per dst, register accumulation, no atomics.
__global__ void edge_dst_kernel() {
    int row = (blockIdx.x * blockDim.x + threadIdx.x) >> 5;
    int lane = threadIdx.x & 31;
    if (row >= NN) return;
    const __half2* qr = reinterpret_cast<const __half2*>(g_qk + (size_t)row * 1024);
    float4 q4[4];
#pragma unroll
    for (int h = 0; h < 4; h++) {
        float2 a = __half22float2(qr[h * 64 + lane * 2]);
        float2 b = __half22float2(qr[h * 64 + lane * 2 + 1]);
        q4[h] = make_float4(a.x, a.y, b.x, b.y);
    }

    float4 acc[4];
    float den[4];
#pragma unroll
    for (int h = 0; h < 4; h++) {
        acc[h] = make_float4(0.f, 0.f, 0.f, 0.f);
        den[h] = 0.f;
    }

    int p0 = g_rowptr[row], p1 = g_rowptr[row + 1];
    int nsrc = (p0 < p1) ? g_ssrc[p0] : 0;
    for (int p = p0; p < p1; p++) {
        int src = nsrc;
        if (p + 1 < p1) nsrc = g_ssrc[p + 1];
        const __half2* kr = reinterpret_cast<const __half2*>(
            g_qk + (size_t)src * 1024 + 512);
        const float4* vr = reinterpret_cast<const float4*>(g_vs + (size_t)src * 640);
        float s[4];
        float4 v4[4];
#pragma unroll
        for (int h = 0; h < 4; h++) {
            float2 a = __half22float2(kr[h * 64 + lane * 2]);
            float2 b = __half22float2(kr[h * 64 + lane * 2 + 1]);
            v4[h] = vr[h * 32 + lane];
            s[h] = q4[h].x * a.x + q4[h].y * a.y + q4[h].z * b.x + q4[h].w * b.y;
        }
#pragma unroll
        for (int h = 0; h < 4; h++)
#pragma unroll
            for (int o = 16; o > 0; o >>= 1)
                s[h] += __shfl_xor_sync(0xffffffffu, s[h], o);
#pragma unroll
        for (int h = 0; h < 4; h++) {
            float ex = expf(s[h] * 0.0883883476483184f);  // 1/sqrt(128)
            den[h] += ex;
            acc[h].x += ex * v4[h].x; acc[h].y += ex * v4[h].y;
            acc[h].z += ex * v4[h].z; acc[h].w += ex * v4[h].w;
        }
    }

    float4 o = make_float4(0.f, 0.f, 0.f, 0.f);
#pragma unroll
    for (int h = 0; h < 4; h++) {
        if (den[h] > 0.f) {
            float inv = 0.25f / den[h];
            o.x += acc[h].x * inv; o.y += acc[h].y * inv;
            o.z += acc[h].z * inv; o.w += acc[h].w * inv;
        }
    }
    reinterpret_cast<float4*>(g_gout + (size_t)row * DD)[lane] = o;
}

// ---------------- fp16x2 mma.sync GEMM ----------------
// C = A[M,K] @ W[Nc,K]^T + bias. A single fp16; W fp16 hi+lo (2 MMAs/step).
// 128x64 block tile, BK=64, 2-stage cp.async double buffer, 2 CTAs/SM.
// OUT: 0=fp32 Cf; 1=fp16 Ch; 2=fp16+relu Ch; 3=mixed (cols<1024 fp16 g_qk
// stride 1024, cols>=1024 fp32 g_vs stride 640).
#define LDK 72
#define OA   0
#define OW_H (128 * LDK * 2)          // 18432
#define OW_L (OW_H + 64 * LDK * 2)    // 27648
#define STG    (OW_L + 64 * LDK * 2)  // 36864 per stage
#define SM_TOT (2 * STG)              // 73728 bytes

template<int OUT>
__global__ __launch_bounds__(256, 2) void gemm_fp16(
    const __half* __restrict__ A,
    const __half* __restrict__ Wh, const __half* __restrict__ Wl,
    const float* __restrict__ bias,
    float* __restrict__ Cf, __half* __restrict__ Ch,
    int M, int Nc, int K)
{
    extern __shared__ char smem[];
    const uint32_t smb = (uint32_t)__cvta_generic_to_shared(smem);

    const int tid  = threadIdx.x;
    const int lane = tid & 31;
    const int w    = tid >> 5;
    const int wm   = w & 3;
    const int wn   = w >> 2;
    const int bm   = blockIdx.y * 128;
    const int bn   = blockIdx.x * 64;

    const int lrow = lane & 7;
    const int quad = lane >> 3;
    const int a_roff = lrow + ((quad & 1) << 3);
    const int a_coff = (quad >> 1) << 3;
    const int b_roff = lrow + ((quad >> 1) << 3);
    const int b_coff = (quad & 1) << 3;

    float acc[2][4][4];
#pragma unroll
    for (int i = 0; i < 2; i++)
#pragma unroll
        for (int j = 0; j < 4; j++)
#pragma unroll
            for (int t = 0; t < 4; t++) acc[i][j][t] = 0.f;

    const int s_row = tid >> 3;         // 0..31
    const int s_c8  = (tid & 7) * 8;    // 8-half chunks (16B)

    auto stage_fn = [&](int s, int k0) {
        uint32_t base = smb + s * STG;
#pragma unroll
        for (int it = 0; it < 4; it++) {
            int row = s_row + it * 32;
            int ga = bm + row; if (ga >= M) ga = M - 1;
            cp16(base + OA + (row * LDK + s_c8) * 2,
                 A + (size_t)ga * K + k0 + s_c8);
        }
#pragma unroll
        for (int it = 0; it < 2; it++) {
            int row = s_row + it * 32;
            uint32_t d = base + (row * LDK + s_c8) * 2;
            size_t woff = (size_t)(bn + row) * K + k0 + s_c8;
            cp16(d + OW_H, Wh + woff);
            cp16(d + OW_L, Wl + woff);
        }
        asm volatile("cp.async.commit_group;");
    };

    const int nCh = K >> 6;
    stage_fn(0, 0);

    for (int c = 0; c < nCh; c++) {
        if (c + 1 < nCh) {
            stage_fn((c + 1) & 1, (c + 1) << 6);
            asm volatile("cp.async.wait_group 1;");
        } else {
            asm volatile("cp.async.wait_group 0;");
        }
        __syncthreads();

        uint32_t base = smb + (c & 1) * STG;
#pragma unroll
        for (int ks = 0; ks < 64; ks += 16) {
            uint32_t af[2][4], bhf[4][2], blf[4][2];
#pragma unroll
            for (int i = 0; i < 2; i++) {
                uint32_t off = (uint32_t)(((wm * 32 + i * 16 + a_roff) * LDK
                                           + ks + a_coff) * 2);
                ldsm_x4(af[i][0], af[i][1], af[i][2], af[i][3], base + OA + off);
            }
#pragma unroll
            for (int jp = 0; jp < 2; jp++) {
                uint32_t off = (uint32_t)(((wn * 32 + jp * 16 + b_roff) * LDK
                                           + ks + b_coff) * 2);
                ldsm_x4(bhf[2 * jp][0], bhf[2 * jp][1],
                        bhf[2 * jp + 1][0], bhf[2 * jp + 1][1],
                        base + OW_H + off);
                ldsm_x4(blf[2 * jp][0], blf[2 * jp][1],
                        blf[2 * jp + 1][0], blf[2 * jp + 1][1],
                        base + OW_L + off);
            }
#pragma unroll
            for (int i = 0; i < 2; i++)
#pragma unroll
                for (int j = 0; j < 4; j++) {
                    mma_f16(acc[i][j], af[i], bhf[j]);
                    mma_f16(acc[i][j], af[i], blf[j]);
                }
        }
        __syncthreads();
    }

    const int qr = lane >> 2;
    const int kq = (lane & 3) * 2;
#pragma unroll
    for (int i = 0; i < 2; i++) {
        int r0 = bm + wm * 32 + i * 16 + qr;
#pragma unroll
        for (int j = 0; j < 4; j++) {
            int c = bn + wn * 32 + j * 8 + kq;
            float b0 = bias[c], b1 = bias[c + 1];
            float v0 = acc[i][j][0] + b0, v1 = acc[i][j][1] + b1;
            float v2 = acc[i][j][2] + b0, v3 = acc[i][j][3] + b1;
            if (OUT == 2) {
                v0 = fmaxf(v0, 0.f); v1 = fmaxf(v1, 0.f);
                v2 = fmaxf(v2, 0.f); v3 = fmaxf(v3, 0.f);
            }
#pragma unroll
            for (int hrow = 0; hrow < 2; hrow++) {
                int r = r0 + hrow * 8;
                if (r >= M) continue;
                float va = hrow ? v2 : v0;
                float vb = hrow ? v3 : v1;
                if (OUT == 0) {
                    *reinterpret_cast<float2*>(Cf + (size_t)r * Nc + c) =
                        make_float2(va, vb);
                } else if (OUT == 1 || OUT == 2) {
                    *reinterpret_cast<__half2*>(Ch + (size_t)r * Nc + c) =
                        __floats2half2_rn(va, vb);
                } else { // OUT == 3: mixed q|k fp16 / v|skip fp32
                    if (c < 1024)
                        *reinterpret_cast<__half2*>(Ch + (size_t)r * 1024 + c) =
                            __floats2half2_rn(va, vb);
                    else
                        *reinterpret_cast<float2*>(Cf + (size_t)r * 640 + (c - 1024)) =
                            make_float2(va, vb);
                }
            }
        }
    }
}

// ---------------- layernorm ----------------
__device__ __forceinline__ float4 ln_core(float4 vv, int lane,
                                          const float* __restrict__ g,
                                          const float* __restrict__ b) {
    float sum = vv.x + vv.y + vv.z + vv.w;
    float sq = vv.x * vv.x + vv.y * vv.y + vv.z * vv.z + vv.w * vv.w;
#pragma unroll
    for (int o = 16; o > 0; o >>= 1) {
        sum += __shfl_xor_sync(0xffffffffu, sum, o);
        sq  += __shfl_xor_sync(0xffffffffu, sq, o);
    }
    float mu = sum * (1.f / 128.f);
    float var = sq * (1.f / 128.f) - mu * mu;
    float rstd = rsqrtf(var + 1e-5f);
    float4 gv = reinterpret_cast<const float4*>(g)[lane];
    float4 bv = reinterpret_cast<const float4*>(b)[lane];
    float4 o;
    o.x = (vv.x - mu) * rstd * gv.x + bv.x;
    o.y = (vv.y - mu) * rstd * gv.y + bv.y;
    o.z = (vv.z - mu) * rstd * gv.z + bv.z;
    o.w = (vv.w - mu) * rstd * gv.w + bv.w;
    return o;
}

// x2 = LN2(LN1(x + gout + skip) + tout); emits x2 fp32 + fp16
__global__ void ln12_kernel(const float* __restrict__ x,
                            const float* __restrict__ ln1g, const float* __restrict__ ln1b,
                            const float* __restrict__ ln2g, const float* __restrict__ ln2b) {
    int row = (blockIdx.x * blockDim.x + threadIdx.x) >> 5;
    int lane = threadIdx.x & 31;
    if (row >= NN) return;
    float4 xv = reinterpret_cast<const float4*>(x + (size_t)row * DD)[lane];
    float4 sv = reinterpret_cast<const float4*>(g_vs + (size_t)row * 640 + 512)[lane];
    float4 gv = reinterpret_cast<const float4*>(g_gout + (size_t)row * DD)[lane];
    float4 vv = make_float4(xv.x + sv.x + gv.x, xv.y + sv.y + gv.y,
                            xv.z + sv.z + gv.z, xv.w + sv.w + gv.w);
    float4 o1 = ln_core(vv, lane, ln1g, ln1b);
    float4 tv = reinterpret_cast<const float4*>(g_tout + (size_t)row * DD)[lane];
    float4 v2 = make_float4(o1.x + tv.x, o1.y + tv.y, o1.z + tv.z, o1.w + tv.w);
    float4 o2 = ln_core(v2, lane, ln2g, ln2b);
    reinterpret_cast<float4*>(g_x2 + (size_t)row * DD)[lane] = o2;
    size_t base = (size_t)row * DD + lane * 4;
    *reinterpret_cast<__half2*>(g_x2f + base)     = __floats2half2_rn(o2.x, o2.y);
    *reinterpret_cast<__half2*>(g_x2f + base + 2) = __floats2half2_rn(o2.z, o2.w);
}

// out = LN(a + b)
__global__ void ln_add_kernel(const float* __restrict__ a, const float* __restrict__ bb,
                              const float* __restrict__ g, const float* __restrict__ beta,
                              float* __restrict__ out) {
    int row = (blockIdx.x * blockDim.x + threadIdx.x) >> 5;
    int lane = threadIdx.x & 31;
    if (row >= NN) return;
    float4 av = reinterpret_cast<const float4*>(a + (size_t)row * DD)[lane];
    float4 bv = reinterpret_cast<const float4*>(bb + (size_t)row * DD)[lane];
    float4 vv = make_float4(av.x + bv.x, av.y + bv.y, av.z + bv.z, av.w + bv.w);
    float4 o = ln_core(vv, lane, g, beta);
    reinterpret_cast<float4*>(out + (size_t)row * DD)[lane] = o;
}

// ---------------- launch ----------------
static void* sym(const void* s) { void* p = nullptr; cudaGetSymbolAddress(&p, s); return p; }

extern "C" void kernel_launch(void* const* d_in, const int* in_sizes, int n_in,
                              void* d_out, int out_size)
{
    const float* x    = (const float*)d_in[0];
    const float* te   = (const float*)d_in[1];
    const float* gq_w = (const float*)d_in[2];  const float* gq_b = (const float*)d_in[3];
    const float* gk_w = (const float*)d_in[4];  const float* gk_b = (const float*)d_in[5];
    const float* gv_w = (const float*)d_in[6];  const float* gv_b = (const float*)d_in[7];
    const float* gs_w = (const float*)d_in[8];  const float* gs_b = (const float*)d_in[9];
    // mha_wq/bq, mha_wk/bk dead: softmax over one kv position is exactly 1.
    const float* wv   = (const float*)d_in[14]; const float* bv   = (const float*)d_in[15];
    const float* wo   = (const float*)d_in[16]; const float* bo   = (const float*)d_in[17];
    const float* w1   = (const float*)d_in[18]; const float* b1   = (const float*)d_in[19];
    const float* w2   = (const float*)d_in[20]; const float* b2   = (const float*)d_in[21];
    const float* ln1g = (const float*)d_in[22]; const float* ln1b = (const float*)d_in[23];
    const float* ln2g = (const float*)d_in[24]; const float* ln2b = (const float*)d_in[25];
    const float* ln3g = (const float*)d_in[26]; const float* ln3b = (const float*)d_in[27];
    const int*   ei   = (const int*)d_in[28];
    float* out = (float*)d_out;

    float* vs_p   = (float*)sym(g_vs);
    float* tout_p = (float*)sym(g_tout);
    float* x2_p   = (float*)sym(g_x2);
    float* ffn_p  = (float*)sym(g_ffn);
    float* bf_p   = (float*)sym(g_bias_f);
    float* wc_p   = (float*)sym(g_wc);
    float* bc_p   = (float*)sym(g_bc);

    __half* qk_p = (__half*)sym(g_qk);
    __half* xf   = (__half*)sym(g_xf);
    __half* tef  = (__half*)sym(g_tef);
    __half* x2f  = (__half*)sym(g_x2f);
    __half* hf   = (__half*)sym(g_hf);
    __half* wfh  = (__half*)sym(g_wfh); __half* wfl = (__half*)sym(g_wfl);
    __half* wch  = (__half*)sym(g_wch); __half* wcl = (__half*)sym(g_wcl);
    __half* w1h  = (__half*)sym(g_w1h); __half* w1l = (__half*)sym(g_w1l);
    __half* w2h  = (__half*)sym(g_w2h); __half* w2l = (__half*)sym(g_w2l);

    cudaFuncSetAttribute(gemm_fp16<0>, cudaFuncAttributeMaxDynamicSharedMemorySize, SM_TOT);
    cudaFuncSetAttribute(gemm_fp16<2>, cudaFuncAttributeMaxDynamicSharedMemorySize, SM_TOT);
    cudaFuncSetAttribute(gemm_fp16<3>, cudaFuncAttributeMaxDynamicSharedMemorySize, SM_TOT);

    const int MB = (NN + 127) / 128;       // 157
    const int NSCAN = (NN + 1023) / 1024;  // 20

    setup_kernel<<<(NN + 255) / 256, 256>>>(gq_b, gk_b, gv_b, gs_b);
    compose_temporal<<<128, 128>>>(wo, wv, bv, bo);

    // CSR build
    hist_kernel<<<(EE + 255) / 256, 256>>>(ei);
    scanA_kernel<<<NSCAN, 1024>>>();
    scanC_kernel<<<(NN + 255) / 256, 256>>>();
    fill_kernel<<<(EE + 255) / 256, 256>>>(ei);

    AJs ajobs;
    ajobs.j[0] = {x,  xf,  NN * DD / 4};
    ajobs.j[1] = {te, tef, NN * DD / 4};
    conv_a<<<dim3(80, 2), 256>>>(ajobs);

    WJs wjobs;
    wjobs.j[0] = {gq_w, wfh,              wfl,              512 * 128 / 4};
    wjobs.j[1] = {gk_w, wfh + 512 * 128,  wfl + 512 * 128,  512 * 128 / 4};
    wjobs.j[2] = {gv_w, wfh + 1024 * 128, wfl + 1024 * 128, 512 * 128 / 4};
    wjobs.j[3] = {gs_w, wfh + 1536 * 128, wfl + 1536 * 128, 128 * 128 / 4};
    wjobs.j[4] = {wc_p, wch, wcl, 128 * 128 / 4};
    wjobs.j[5] = {w1,   w1h, w1l, 512 * 128 / 4};
    wjobs.j[6] = {w2,   w2h, w2l, 128 * 512 / 4};
    conv_w<<<dim3(48, 7), 256>>>(wjobs);

    // fused q|k|v|skip projection: mixed output (q,k fp16; v,skip fp32)
    gemm_fp16<3><<<dim3(NFUSE / 64, MB), 256, SM_TOT>>>(
        xf, wfh, wfl, bf_p, vs_p, qk_p, NN, NFUSE, 128);
    // temporal (composed): tout = te @ Wc^T + bc
    gemm_fp16<0><<<dim3(2, MB), 256, SM_TOT>>>(
        tef, wch, wcl, bc_p, tout_p, nullptr, NN, 128, 128);

    // graph attention
    edge_dst_kernel<<<(NN + 7) / 8, 256>>>();

    // x2 = LN2(LN1(x+gout+skip) + tout)
    ln12_kernel<<<(NN + 7) / 8, 256>>>(x, ln1g, ln1b, ln2g, ln2b);
    // FFN
    gemm_fp16<2><<<dim3(8, MB), 256, SM_TOT>>>(
        x2f, w1h, w1l, b1, nullptr, hf, NN, 512, 128);
    gemm_fp16<0><<<dim3(2, MB), 256, SM_TOT>>>(
        hf, w2h, w2l, b2, ffn_p, nullptr, NN, 128, 512);
    ln_add_kernel<<<(NN + 7) / 8, 256>>>(x2_p, ffn_p, ln3g, ln3b, out);
}

// round 15
// speedup vs baseline: 1.8060x; 1.1421x over previous
#include <cuda_runtime.h>
#include <cuda_fp16.h>
#include <math.h>
#include <math_constants.h>
#include <stdint.h>

#define NN 20000
#define EE 160000
#define DD 128
#define NFUSE 1664   // 512(q)+512(k)+512(v)+128(skip)

// ---------------- scratch (static device globals; no allocation) ----------------
__device__ __half g_qkv[NN * 1536];    // q|k|v fp16, row stride 1536
__device__ float  g_skip[NN * DD];     // skip fp32
__device__ float g_gout[NN * DD];
__device__ float g_tout[NN * DD];
__device__ float g_x2[NN * DD];
__device__ float g_ffn[NN * DD];
__device__ float g_bias_f[NFUSE];
__device__ float g_wc[128 * 128];      // composed temporal weight Wo@Wv
__device__ float g_bc[128];            // composed temporal bias Wo@bv+bo
// CSR scratch
__device__ int g_deg[NN];
__device__ int g_rowptr[NN + 1];
__device__ int g_cursor[NN];
__device__ int g_blocksum[32];
__device__ int g_ssrc[EE];

// fp16 operand buffers (single precision fp16 both sides)
__device__ __half g_xf[NN * DD];
__device__ __half g_tef[NN * DD];
__device__ __half g_x2f[NN * DD];
__device__ __half g_hf[NN * 512];
__device__ __half g_wf[NFUSE * 128];
__device__ __half g_wcf[128 * 128];
__device__ __half g_w1f[512 * 128];
__device__ __half g_w2f[128 * 512];

// ---------------- helpers ----------------
__device__ __forceinline__ void mma_f16(float* c, const uint32_t* a, const uint32_t* b) {
    asm volatile(
        "mma.sync.aligned.m16n8k16.row.col.f32.f16.f16.f32 "
        "{%0,%1,%2,%3}, {%4,%5,%6,%7}, {%8,%9}, {%0,%1,%2,%3};"
        : "+f"(c[0]), "+f"(c[1]), "+f"(c[2]), "+f"(c[3])
        : "r"(a[0]), "r"(a[1]), "r"(a[2]), "r"(a[3]), "r"(b[0]), "r"(b[1]));
}

__device__ __forceinline__ void ldsm_x4(uint32_t& r0, uint32_t& r1, uint32_t& r2,
                                        uint32_t& r3, uint32_t addr) {
    asm volatile("ldmatrix.sync.aligned.m8n8.x4.shared.b16 {%0,%1,%2,%3}, [%4];"
                 : "=r"(r0), "=r"(r1), "=r"(r2), "=r"(r3) : "r"(addr));
}

__device__ __forceinline__ void cp16(uint32_t dst, const void* src) {
    asm volatile("cp.async.cg.shared.global [%0], [%1], 16;" :: "r"(dst), "l"(src));
}

// ---------------- setup: deg=0 + concat graph biases ----------------
__global__ void setup_kernel(const float* a, const float* b,
                             const float* c, const float* d) {
    int i = blockIdx.x * blockDim.x + threadIdx.x;
    if (i < NN) g_deg[i] = 0;
    if (i < 512) g_bias_f[i] = a[i];
    else if (i < 1024) g_bias_f[i] = b[i - 512];
    else if (i < 1536) g_bias_f[i] = c[i - 1024];
    else if (i < NFUSE) g_bias_f[i] = d[i - 1536];
}

// ---------------- temporal weight composition ----------------
__global__ void compose_temporal(const float* __restrict__ wo,
                                 const float* __restrict__ wv,
                                 const float* __restrict__ bv,
                                 const float* __restrict__ bo) {
    int i = blockIdx.x;
    int j = threadIdx.x;
    __shared__ float wo_s[128];
    __shared__ float bs[4];
    wo_s[j] = wo[i * 128 + j];
    __syncthreads();
    float sum = 0.f;
#pragma unroll 8
    for (int k = 0; k < 128; k++) sum += wo_s[k] * wv[k * 128 + j];
    g_wc[i * 128 + j] = sum;
    float bb = wo_s[j] * bv[j];
#pragma unroll
    for (int o = 16; o > 0; o >>= 1) bb += __shfl_xor_sync(0xffffffffu, bb, o);
    if ((j & 31) == 0) bs[j >> 5] = bb;
    __syncthreads();
    if (j == 0) g_bc[i] = bs[0] + bs[1] + bs[2] + bs[3] + bo[i];
}

// ---------------- batched fp32 -> fp16 conversion ----------------
struct AJ { const float* s; __half* d; int n4; };
struct AJs { AJ j[9]; };
__global__ void conv_a(AJs jobs) {
    AJ job = jobs.j[blockIdx.y];
    int stride = gridDim.x * blockDim.x;
    for (int i = blockIdx.x * blockDim.x + threadIdx.x; i < job.n4; i += stride) {
        float4 v = reinterpret_cast<const float4*>(job.s)[i];
        reinterpret_cast<__half2*>(job.d)[2 * i]     = __floats2half2_rn(v.x, v.y);
        reinterpret_cast<__half2*>(job.d)[2 * i + 1] = __floats2half2_rn(v.z, v.w);
    }
}

// ---------------- CSR build ----------------
__global__ void hist_kernel(const int* __restrict__ ei) {
    int e = blockIdx.x * blockDim.x + threadIdx.x;
    if (e < EE) atomicAdd(&g_deg[ei[EE + e]], 1);
}
__global__ void scanA_kernel() {
    int t = threadIdx.x, b = blockIdx.x;
    int idx = b * 1024 + t;
    int v = (idx < NN) ? g_deg[idx] : 0;
    int lane = t & 31, wid = t >> 5;
    int x = v;
#pragma unroll
    for (int o = 1; o < 32; o <<= 1) {
        int y = __shfl_up_sync(0xffffffffu, x, o);
        if (lane >= o) x += y;
    }
    __shared__ int wsum[32];
    if (lane == 31) wsum[wid] = x;
    __syncthreads();
    if (wid == 0) {
        int w = wsum[lane];
#pragma unroll
        for (int o = 1; o < 32; o <<= 1) {
            int y = __shfl_up_sync(0xffffffffu, w, o);
            if (lane >= o) w += y;
        }
        wsum[lane] = w;
    }
    __syncthreads();
    int incl = x + (wid > 0 ? wsum[wid - 1] : 0);
    if (idx < NN) g_rowptr[idx] = incl - v;
    if (t == 1023) g_blocksum[b] = incl;
}
__global__ void scanC_kernel() {
    __shared__ int base_s;
    if (threadIdx.x == 0) {
        int nb = blockIdx.x >> 2;
        int s = 0;
        for (int k = 0; k < nb; k++) s += g_blocksum[k];
        base_s = s;
    }
    __syncthreads();
    int i = blockIdx.x * 256 + threadIdx.x;
    if (i < NN) {
        int r = g_rowptr[i] + base_s;
        g_rowptr[i] = r;
        g_cursor[i] = r;
    }
    if (i == 0) g_rowptr[NN] = EE;
}
__global__ void fill_kernel(const int* __restrict__ ei) {
    int e = blockIdx.x * blockDim.x + threadIdx.x;
    if (e >= EE) return;
    int dst = ei[EE + e];
    int pos = atomicAdd(&g_cursor[dst], 1);
    g_ssrc[pos] = ei[e];
}

// ---------------- per-dst edge aggregation (q/k/v fp16) ----------------
__global__ void edge_dst_kernel() {
    int row = (blockIdx.x * blockDim.x + threadIdx.x) >> 5;
    int lane = threadIdx.x & 31;
    if (row >= NN) return;
    const __half2* qr = reinterpret_cast<const __half2*>(g_qkv + (size_t)row * 1536);
    float4 q4[4];
#pragma unroll
    for (int h = 0; h < 4; h++) {
        float2 a = __half22float2(qr[h * 64 + lane * 2]);
        float2 b = __half22float2(qr[h * 64 + lane * 2 + 1]);
        q4[h] = make_float4(a.x, a.y, b.x, b.y);
    }

    float4 acc[4];
    float den[4];
#pragma unroll
    for (int h = 0; h < 4; h++) {
        acc[h] = make_float4(0.f, 0.f, 0.f, 0.f);
        den[h] = 0.f;
    }

    int p0 = g_rowptr[row], p1 = g_rowptr[row + 1];
    int nsrc = (p0 < p1) ? g_ssrc[p0] : 0;
    for (int p = p0; p < p1; p++) {
        int src = nsrc;
        if (p + 1 < p1) nsrc = g_ssrc[p + 1];
        const __half2* kr = reinterpret_cast<const __half2*>(
            g_qkv + (size_t)src * 1536 + 512);
        const __half2* vr = kr + 256;   // +512 halves
        float s[4];
        float4 v4[4];
#pragma unroll
        for (int h = 0; h < 4; h++) {
            float2 ka = __half22float2(kr[h * 64 + lane * 2]);
            float2 kb = __half22float2(kr[h * 64 + lane * 2 + 1]);
            float2 va = __half22float2(vr[h * 64 + lane * 2]);
            float2 vb = __half22float2(vr[h * 64 + lane * 2 + 1]);
            v4[h] = make_float4(va.x, va.y, vb.x, vb.y);
            s[h] = q4[h].x * ka.x + q4[h].y * ka.y + q4[h].z * kb.x + q4[h].w * kb.y;
        }
#pragma unroll
        for (int h = 0; h < 4; h++)
#pragma unroll
            for (int o = 16; o > 0; o >>= 1)
                s[h] += __shfl_xor_sync(0xffffffffu, s[h], o);
#pragma unroll
        for (int h = 0; h < 4; h++) {
            float ex = expf(s[h] * 0.0883883476483184f);  // 1/sqrt(128)
            den[h] += ex;
            acc[h].x += ex * v4[h].x; acc[h].y += ex * v4[h].y;
            acc[h].z += ex * v4[h].z; acc[h].w += ex * v4[h].w;
        }
    }

    float4 o = make_float4(0.f, 0.f, 0.f, 0.f);
#pragma unroll
    for (int h = 0; h < 4; h++) {
        if (den[h] > 0.f) {
            float inv = 0.25f / den[h];
            o.x += acc[h].x * inv; o.y += acc[h].y * inv;
            o.z += acc[h].z * inv; o.w += acc[h].w * inv;
        }
    }
    reinterpret_cast<float4*>(g_gout + (size_t)row * DD)[lane] = o;
}

// ---------------- fp16 mma.sync GEMM (single precision both operands) ----------------
// C = A[M,K] @ W[Nc,K]^T + bias. 1 MMA per k-step. 128x64 block tile, BK=64,
// 2-stage cp.async double buffer, 2 CTAs/SM.
// OUT: 0=fp32 Cf; 2=fp16+relu Ch; 3=mixed (cols<1536 fp16 g_qkv stride 1536,
// cols>=1536 fp32 g_skip stride 128).
#define LDK 72
#define OA   0
#define OW   (128 * LDK * 2)          // 18432
#define STG    (OW + 64 * LDK * 2)    // 27648 per stage
#define SM_TOT (2 * STG)              // 55296 bytes

template<int OUT>
__global__ __launch_bounds__(256, 2) void gemm_fp16(
    const __half* __restrict__ A,
    const __half* __restrict__ W,
    const float* __restrict__ bias,
    float* __restrict__ Cf, __half* __restrict__ Ch,
    int M, int Nc, int K)
{
    extern __shared__ char smem[];
    const uint32_t smb = (uint32_t)__cvta_generic_to_shared(smem);

    const int tid  = threadIdx.x;
    const int lane = tid & 31;
    const int w    = tid >> 5;
    const int wm   = w & 3;
    const int wn   = w >> 2;
    const int bm   = blockIdx.y * 128;
    const int bn   = blockIdx.x * 64;

    const int lrow = lane & 7;
    const int quad = lane >> 3;
    const int a_roff = lrow + ((quad & 1) << 3);
    const int a_coff = (quad >> 1) << 3;
    const int b_roff = lrow + ((quad >> 1) << 3);
    const int b_coff = (quad & 1) << 3;

    float acc[2][4][4];
#pragma unroll
    for (int i = 0; i < 2; i++)
#pragma unroll
        for (int j = 0; j < 4; j++)
#pragma unroll
            for (int t = 0; t < 4; t++) acc[i][j][t] = 0.f;

    const int s_row = tid >> 3;
    const int s_c8  = (tid & 7) * 8;

    auto stage_fn = [&](int s, int k0) {
        uint32_t base = smb + s * STG;
#pragma unroll
        for (int it = 0; it < 4; it++) {
            int row = s_row + it * 32;
            int ga = bm + row; if (ga >= M) ga = M - 1;
            cp16(base + OA + (row * LDK + s_c8) * 2,
                 A + (size_t)ga * K + k0 + s_c8);
        }
#pragma unroll
        for (int it = 0; it < 2; it++) {
            int row = s_row + it * 32;
            cp16(base + OW + (row * LDK + s_c8) * 2,
                 W + (size_t)(bn + row) * K + k0 + s_c8);
        }
        asm volatile("cp.async.commit_group;");
    };

    const int nCh = K >> 6;
    stage_fn(0, 0);

    for (int c = 0; c < nCh; c++) {
        if (c + 1 < nCh) {
            stage_fn((c + 1) & 1, (c + 1) << 6);
            asm volatile("cp.async.wait_group 1;");
        } else {
            asm volatile("cp.async.wait_group 0;");
        }
        __syncthreads();

        uint32_t base = smb + (c & 1) * STG;
#pragma unroll
        for (int ks = 0; ks < 64; ks += 16) {
            uint32_t af[2][4], bf[4][2];
#pragma unroll
            for (int i = 0; i < 2; i++) {
                uint32_t off = (uint32_t)(((wm * 32 + i * 16 + a_roff) * LDK
                                           + ks + a_coff) * 2);
                ldsm_x4(af[i][0], af[i][1], af[i][2], af[i][3], base + OA + off);
            }
#pragma unroll
            for (int jp = 0; jp < 2; jp++) {
                uint32_t off = (uint32_t)(((wn * 32 + jp * 16 + b_roff) * LDK
                                           + ks + b_coff) * 2);
                ldsm_x4(bf[2 * jp][0], bf[2 * jp][1],
                        bf[2 * jp + 1][0], bf[2 * jp + 1][1],
                        base + OW + off);
            }
#pragma unroll
            for (int i = 0; i < 2; i++)
#pragma unroll
                for (int j = 0; j < 4; j++)
                    mma_f16(acc[i][j], af[i], bf[j]);
        }
        __syncthreads();
    }

    const int qr = lane >> 2;
    const int kq = (lane & 3) * 2;
#pragma unroll
    for (int i = 0; i < 2; i++) {
        int r0 = bm + wm * 32 + i * 16 + qr;
#pragma unroll
        for (int j = 0; j < 4; j++) {
            int c = bn + wn * 32 + j * 8 + kq;
            float b0 = bias[c], b1 = bias[c + 1];
            float v0 = acc[i][j][0] + b0, v1 = acc[i][j][1] + b1;
            float v2 = acc[i][j][2] + b0, v3 = acc[i][j][3] + b1;
            if (OUT == 2) {
                v0 = fmaxf(v0, 0.f); v1 = fmaxf(v1, 0.f);
                v2 = fmaxf(v2, 0.f); v3 = fmaxf(v3, 0.f);
            }
#pragma unroll
            for (int hrow = 0; hrow < 2; hrow++) {
                int r = r0 + hrow * 8;
                if (r >= M) continue;
                float va = hrow ? v2 : v0;
                float vb = hrow ? v3 : v1;
                if (OUT == 0) {
                    *reinterpret_cast<float2*>(Cf + (size_t)r * Nc + c) =
                        make_float2(va, vb);
                } else if (OUT == 2) {
                    *reinterpret_cast<__half2*>(Ch + (size_t)r * Nc + c) =
                        __floats2half2_rn(va, vb);
                } else { // OUT == 3: q|k|v fp16 / skip fp32
                    if (c < 1536)
                        *reinterpret_cast<__half2*>(Ch + (size_t)r * 1536 + c) =
                            __floats2half2_rn(va, vb);
                    else
                        *reinterpret_cast<float2*>(Cf + (size_t)r * DD + (c - 1536)) =
                            make_float2(va, vb);
                }
            }
        }
    }
}

// ---------------- layernorm ----------------
__device__ __forceinline__ float4 ln_core(float4 vv, int lane,
                                          const float* __restrict__ g,
                                          const float* __restrict__ b) {
    float sum = vv.x + vv.y + vv.z + vv.w;
    float sq = vv.x * vv.x + vv.y * vv.y + vv.z * vv.z + vv.w * vv.w;
#pragma unroll
    for (int o = 16; o > 0; o >>= 1) {
        sum += __shfl_xor_sync(0xffffffffu, sum, o);
        sq  += __shfl_xor_sync(0xffffffffu, sq, o);
    }
    float mu = sum * (1.f / 128.f);
    float var = sq * (1.f / 128.f) - mu * mu;
    float rstd = rsqrtf(var + 1e-5f);
    float4 gv = reinterpret_cast<const float4*>(g)[lane];
    float4 bv = reinterpret_cast<const float4*>(b)[lane];
    float4 o;
    o.x = (vv.x - mu) * rstd * gv.x + bv.x;
    o.y = (vv.y - mu) * rstd * gv.y + bv.y;
    o.z = (vv.z - mu) * rstd * gv.z + bv.z;
    o.w = (vv.w - mu) * rstd * gv.w + bv.w;
    return o;
}

// x2 = LN2(LN1(x + gout + skip) + tout); emits x2 fp32 + fp16
__global__ void ln12_kernel(const float* __restrict__ x,
                            const float* __restrict__ ln1g, const float* __restrict__ ln1b,
                            const float* __restrict__ ln2g, const float* __restrict__ ln2b) {
    int row = (blockIdx.x * blockDim.x + threadIdx.x) >> 5;
    int lane = threadIdx.x & 31;
    if (row >= NN) return;
    float4 xv = reinterpret_cast<const float4*>(x + (size_t)row * DD)[lane];
    float4 sv = reinterpret_cast<const float4*>(g_skip + (size_t)row * DD)[lane];
    float4 gv = reinterpret_cast<const float4*>(g_gout + (size_t)row * DD)[lane];
    float4 vv = make_float4(xv.x + sv.x + gv.x, xv.y + sv.y + gv.y,
                            xv.z + sv.z + gv.z, xv.w + sv.w + gv.w);
    float4 o1 = ln_core(vv, lane, ln1g, ln1b);
    float4 tv = reinterpret_cast<const float4*>(g_tout + (size_t)row * DD)[lane];
    float4 v2 = make_float4(o1.x + tv.x, o1.y + tv.y, o1.z + tv.z, o1.w + tv.w);
    float4 o2 = ln_core(v2, lane, ln2g, ln2b);
    reinterpret_cast<float4*>(g_x2 + (size_t)row * DD)[lane] = o2;
    size_t base = (size_t)row * DD + lane * 4;
    *reinterpret_cast<__half2*>(g_x2f + base)     = __floats2half2_rn(o2.x, o2.y);
    *reinterpret_cast<__half2*>(g_x2f + base + 2) = __floats2half2_rn(o2.z, o2.w);
}

// out = LN(a + b)
__global__ void ln_add_kernel(const float* __restrict__ a, const float* __restrict__ bb,
                              const float* __restrict__ g, const float* __restrict__ beta,
                              float* __restrict__ out) {
    int row = (blockIdx.x * blockDim.x + threadIdx.x) >> 5;
    int lane = threadIdx.x & 31;
    if (row >= NN) return;
    float4 av = reinterpret_cast<const float4*>(a + (size_t)row * DD)[lane];
    float4 bv = reinterpret_cast<const float4*>(bb + (size_t)row * DD)[lane];
    float4 vv = make_float4(av.x + bv.x, av.y + bv.y, av.z + bv.z, av.w + bv.w);
    float4 o = ln_core(vv, lane, g, beta);
    reinterpret_cast<float4*>(out + (size_t)row * DD)[lane] = o;
}

// ---------------- launch ----------------
static void* sym(const void* s) { void* p = nullptr; cudaGetSymbolAddress(&p, s); return p; }

extern "C" void kernel_launch(void* const* d_in, const int* in_sizes, int n_in,
                              void* d_out, int out_size)
{
    const float* x    = (const float*)d_in[0];
    const float* te   = (const float*)d_in[1];
    const float* gq_w = (const float*)d_in[2];  const float* gq_b = (const float*)d_in[3];
    const float* gk_w = (const float*)d_in[4];  const float* gk_b = (const float*)d_in[5];
    const float* gv_w = (const float*)d_in[6];  const float* gv_b = (const float*)d_in[7];
    const float* gs_w = (const float*)d_in[8];  const float* gs_b = (const float*)d_in[9];
    // mha_wq/bq, mha_wk/bk dead: softmax over one kv position is exactly 1.
    const float* wv   = (const float*)d_in[14]; const float* bv   = (const float*)d_in[15];
    const float* wo   = (const float*)d_in[16]; const float* bo   = (const float*)d_in[17];
    const float* w1   = (const float*)d_in[18]; const float* b1   = (const float*)d_in[19];
    const float* w2   = (const float*)d_in[20]; const float* b2   = (const float*)d_in[21];
    const float* ln1g = (const float*)d_in[22]; const float* ln1b = (const float*)d_in[23];
    const float* ln2g = (const float*)d_in[24]; const float* ln2b = (const float*)d_in[25];
    const float* ln3g = (const float*)d_in[26]; const float* ln3b = (const float*)d_in[27];
    const int*   ei   = (const int*)d_in[28];
    float* out = (float*)d_out;

    float* skip_p = (float*)sym(g_skip);
    float* tout_p = (float*)sym(g_tout);
    float* x2_p   = (float*)sym(g_x2);
    float* ffn_p  = (float*)sym(g_ffn);
    float* bf_p   = (float*)sym(g_bias_f);
    float* wc_p   = (float*)sym(g_wc);
    float* bc_p   = (float*)sym(g_bc);

    __half* qkv_p = (__half*)sym(g_qkv);
    __half* xf   = (__half*)sym(g_xf);
    __half* tef  = (__half*)sym(g_tef);
    __half* x2f  = (__half*)sym(g_x2f);
    __half* hf   = (__half*)sym(g_hf);
    __half* wf   = (__half*)sym(g_wf);
    __half* wcf  = (__half*)sym(g_wcf);
    __half* w1f  = (__half*)sym(g_w1f);
    __half* w2f  = (__half*)sym(g_w2f);

    cudaFuncSetAttribute(gemm_fp16<0>, cudaFuncAttributeMaxDynamicSharedMemorySize, SM_TOT);
    cudaFuncSetAttribute(gemm_fp16<2>, cudaFuncAttributeMaxDynamicSharedMemorySize, SM_TOT);
    cudaFuncSetAttribute(gemm_fp16<3>, cudaFuncAttributeMaxDynamicSharedMemorySize, SM_TOT);

    const int MB = (NN + 127) / 128;       // 157
    const int NSCAN = (NN + 1023) / 1024;  // 20

    setup_kernel<<<(NN + 255) / 256, 256>>>(gq_b, gk_b, gv_b, gs_b);
    compose_temporal<<<128, 128>>>(wo, wv, bv, bo);

    // CSR build
    hist_kernel<<<(EE + 255) / 256, 256>>>(ei);
    scanA_kernel<<<NSCAN, 1024>>>();
    scanC_kernel<<<(NN + 255) / 256, 256>>>();
    fill_kernel<<<(EE + 255) / 256, 256>>>(ei);

    AJs jobs;
    jobs.j[0] = {x,    xf,  NN * DD / 4};
    jobs.j[1] = {te,   tef, NN * DD / 4};
    jobs.j[2] = {gq_w, wf,              512 * 128 / 4};
    jobs.j[3] = {gk_w, wf + 512 * 128,  512 * 128 / 4};
    jobs.j[4] = {gv_w, wf + 1024 * 128, 512 * 128 / 4};
    jobs.j[5] = {gs_w, wf + 1536 * 128, 128 * 128 / 4};
    jobs.j[6] = {wc_p, wcf, 128 * 128 / 4};
    jobs.j[7] = {w1,   w1f, 512 * 128 / 4};
    jobs.j[8] = {w2,   w2f, 128 * 512 / 4};
    conv_a<<<dim3(64, 9), 256>>>(jobs);

    // fused q|k|v|skip projection: mixed output (q,k,v fp16; skip fp32)
    gemm_fp16<3><<<dim3(NFUSE / 64, MB), 256, SM_TOT>>>(
        xf, wf, bf_p, skip_p, qkv_p, NN, NFUSE, 128);
    // temporal (composed): tout = te @ Wc^T + bc
    gemm_fp16<0><<<dim3(2, MB), 256, SM_TOT>>>(
        tef, wcf, bc_p, tout_p, nullptr, NN, 128, 128);

    // graph attention
    edge_dst_kernel<<<(NN + 7) / 8, 256>>>();

    // x2 = LN2(LN1(x+gout+skip) + tout)
    ln12_kernel<<<(NN + 7) / 8, 256>>>(x, ln1g, ln1b, ln2g, ln2b);
    // FFN
    gemm_fp16<2><<<dim3(8, MB), 256, SM_TOT>>>(
        x2f, w1f, b1, nullptr, hf, NN, 512, 128);
    gemm_fp16<0><<<dim3(2, MB), 256, SM_TOT>>>(
        hf, w2f, b2, ffn_p, nullptr, NN, 128, 512);
    ln_add_kernel<<<(NN + 7) / 8, 256>>>(x2_p, ffn_p, ln3g, ln3b, out);
}

// round 16
// speedup vs baseline: 1.9000x; 1.0521x over previous
#include <cuda_runtime.h>
#include <cuda_fp16.h>
#include <math.h>
#include <math_constants.h>
#include <stdint.h>

#define NN 20000
#define EE 160000
#define DD 128
#define NFUSE 1664   // 512(q)+512(k)+512(v)+128(skip)

// ---------------- scratch (static device globals; no allocation) ----------------
__device__ __half g_qkv[NN * 1536];    // q|k|v fp16, row stride 1536
__device__ float  g_skip[NN * DD];     // skip fp32
__device__ float g_gout[NN * DD];
__device__ float g_tout[NN * DD];
__device__ float g_x2[NN * DD];
__device__ float g_ffn[NN * DD];
__device__ float g_bias_f[NFUSE];
__device__ float g_wc[128 * 128];      // composed temporal weight Wo@Wv
__device__ float g_bc[128];            // composed temporal bias Wo@bv+bo
// CSR scratch
__device__ int g_deg[NN];
__device__ int g_rowptr[NN + 1];
__device__ int g_cursor[NN];
__device__ int g_blocksum[32];
__device__ int g_ssrc[EE];

// fp16 operand buffers
__device__ __half g_xf[NN * DD];
__device__ __half g_tef[NN * DD];
__device__ __half g_x2f[NN * DD];
__device__ __half g_hf[NN * 512];
__device__ __half g_wf[NFUSE * 128];
__device__ __half g_wcf[128 * 128];
__device__ __half g_w1f[512 * 128];
__device__ __half g_w2f[128 * 512];

// ---------------- helpers ----------------
__device__ __forceinline__ void mma_f16(float* c, const uint32_t* a, const uint32_t* b) {
    asm volatile(
        "mma.sync.aligned.m16n8k16.row.col.f32.f16.f16.f32 "
        "{%0,%1,%2,%3}, {%4,%5,%6,%7}, {%8,%9}, {%0,%1,%2,%3};"
        : "+f"(c[0]), "+f"(c[1]), "+f"(c[2]), "+f"(c[3])
        : "r"(a[0]), "r"(a[1]), "r"(a[2]), "r"(a[3]), "r"(b[0]), "r"(b[1]));
}

__device__ __forceinline__ void ldsm_x4(uint32_t& r0, uint32_t& r1, uint32_t& r2,
                                        uint32_t& r3, uint32_t addr) {
    asm volatile("ldmatrix.sync.aligned.m8n8.x4.shared.b16 {%0,%1,%2,%3}, [%4];"
                 : "=r"(r0), "=r"(r1), "=r"(r2), "=r"(r3) : "r"(addr));
}

__device__ __forceinline__ void cp16(uint32_t dst, const void* src) {
    asm volatile("cp.async.cg.shared.global [%0], [%1], 16;" :: "r"(dst), "l"(src));
}

// ---------------- setup: deg=0 + concat graph biases ----------------
__global__ void setup_kernel(const float* a, const float* b,
                             const float* c, const float* d) {
    int i = blockIdx.x * blockDim.x + threadIdx.x;
    if (i < NN) g_deg[i] = 0;
    if (i < 512) g_bias_f[i] = a[i];
    else if (i < 1024) g_bias_f[i] = b[i - 512];
    else if (i < 1536) g_bias_f[i] = c[i - 1024];
    else if (i < NFUSE) g_bias_f[i] = d[i - 1536];
}

// ---------------- temporal weight composition ----------------
__global__ void compose_temporal(const float* __restrict__ wo,
                                 const float* __restrict__ wv,
                                 const float* __restrict__ bv,
                                 const float* __restrict__ bo) {
    int i = blockIdx.x;
    int j = threadIdx.x;
    __shared__ float wo_s[128];
    __shared__ float bs[4];
    wo_s[j] = wo[i * 128 + j];
    __syncthreads();
    float sum = 0.f;
#pragma unroll 8
    for (int k = 0; k < 128; k++) sum += wo_s[k] * wv[k * 128 + j];
    g_wc[i * 128 + j] = sum;
    float bb = wo_s[j] * bv[j];
#pragma unroll
    for (int o = 16; o > 0; o >>= 1) bb += __shfl_xor_sync(0xffffffffu, bb, o);
    if ((j & 31) == 0) bs[j >> 5] = bb;
    __syncthreads();
    if (j == 0) g_bc[i] = bs[0] + bs[1] + bs[2] + bs[3] + bo[i];
}

// ---------------- batched fp32 -> fp16 conversion ----------------
struct AJ { const float* s; __half* d; int n4; };
struct AJs { AJ j[9]; };
__global__ void conv_a(AJs jobs) {
    AJ job = jobs.j[blockIdx.y];
    int stride = gridDim.x * blockDim.x;
    for (int i = blockIdx.x * blockDim.x + threadIdx.x; i < job.n4; i += stride) {
        float4 v = reinterpret_cast<const float4*>(job.s)[i];
        reinterpret_cast<__half2*>(job.d)[2 * i]     = __floats2half2_rn(v.x, v.y);
        reinterpret_cast<__half2*>(job.d)[2 * i + 1] = __floats2half2_rn(v.z, v.w);
    }
}

// ---------------- CSR build ----------------
__global__ void hist_kernel(const int* __restrict__ ei) {
    int e = blockIdx.x * blockDim.x + threadIdx.x;
    if (e < EE) atomicAdd(&g_deg[ei[EE + e]], 1);
}
__global__ void scanA_kernel() {
    int t = threadIdx.x, b = blockIdx.x;
    int idx = b * 1024 + t;
    int v = (idx < NN) ? g_deg[idx] : 0;
    int lane = t & 31, wid = t >> 5;
    int x = v;
#pragma unroll
    for (int o = 1; o < 32; o <<= 1) {
        int y = __shfl_up_sync(0xffffffffu, x, o);
        if (lane >= o) x += y;
    }
    __shared__ int wsum[32];
    if (lane == 31) wsum[wid] = x;
    __syncthreads();
    if (wid == 0) {
        int w = wsum[lane];
#pragma unroll
        for (int o = 1; o < 32; o <<= 1) {
            int y = __shfl_up_sync(0xffffffffu, w, o);
            if (lane >= o) w += y;
        }
        wsum[lane] = w;
    }
    __syncthreads();
    int incl = x + (wid > 0 ? wsum[wid - 1] : 0);
    if (idx < NN) g_rowptr[idx] = incl - v;
    if (t == 1023) g_blocksum[b] = incl;
}
__global__ void scanC_kernel() {
    __shared__ int base_s;
    if (threadIdx.x == 0) {
        int nb = blockIdx.x >> 2;
        int s = 0;
        for (int k = 0; k < nb; k++) s += g_blocksum[k];
        base_s = s;
    }
    __syncthreads();
    int i = blockIdx.x * 256 + threadIdx.x;
    if (i < NN) {
        int r = g_rowptr[i] + base_s;
        g_rowptr[i] = r;
        g_cursor[i] = r;
    }
    if (i == 0) g_rowptr[NN] = EE;
}
__global__ void fill_kernel(const int* __restrict__ ei) {
    int e = blockIdx.x * blockDim.x + threadIdx.x;
    if (e >= EE) return;
    int dst = ei[EE + e];
    int pos = atomicAdd(&g_cursor[dst], 1);
    g_ssrc[pos] = ei[e];
}

// ---------------- per-dst edge aggregation (q/k/v fp16) ----------------
__global__ void edge_dst_kernel() {
    int row = (blockIdx.x * blockDim.x + threadIdx.x) >> 5;
    int lane = threadIdx.x & 31;
    if (row >= NN) return;
    const __half2* qr = reinterpret_cast<const __half2*>(g_qkv + (size_t)row * 1536);
    float4 q4[4];
#pragma unroll
    for (int h = 0; h < 4; h++) {
        float2 a = __half22float2(qr[h * 64 + lane * 2]);
        float2 b = __half22float2(qr[h * 64 + lane * 2 + 1]);
        q4[h] = make_float4(a.x, a.y, b.x, b.y);
    }

    float4 acc[4];
    float den[4];
#pragma unroll
    for (int h = 0; h < 4; h++) {
        acc[h] = make_float4(0.f, 0.f, 0.f, 0.f);
        den[h] = 0.f;
    }

    int p0 = g_rowptr[row], p1 = g_rowptr[row + 1];
    int nsrc = (p0 < p1) ? g_ssrc[p0] : 0;
    for (int p = p0; p < p1; p++) {
        int src = nsrc;
        if (p + 1 < p1) nsrc = g_ssrc[p + 1];
        const __half2* kr = reinterpret_cast<const __half2*>(
            g_qkv + (size_t)src * 1536 + 512);
        const __half2* vr = kr + 256;
        float s[4];
        float4 v4[4];
#pragma unroll
        for (int h = 0; h < 4; h++) {
            float2 ka = __half22float2(kr[h * 64 + lane * 2]);
            float2 kb = __half22float2(kr[h * 64 + lane * 2 + 1]);
            float2 va = __half22float2(vr[h * 64 + lane * 2]);
            float2 vb = __half22float2(vr[h * 64 + lane * 2 + 1]);
            v4[h] = make_float4(va.x, va.y, vb.x, vb.y);
            s[h] = q4[h].x * ka.x + q4[h].y * ka.y + q4[h].z * kb.x + q4[h].w * kb.y;
        }
#pragma unroll
        for (int h = 0; h < 4; h++)
#pragma unroll
            for (int o = 16; o > 0; o >>= 1)
                s[h] += __shfl_xor_sync(0xffffffffu, s[h], o);
#pragma unroll
        for (int h = 0; h < 4; h++) {
            float ex = expf(s[h] * 0.0883883476483184f);  // 1/sqrt(128)
            den[h] += ex;
            acc[h].x += ex * v4[h].x; acc[h].y += ex * v4[h].y;
            acc[h].z += ex * v4[h].z; acc[h].w += ex * v4[h].w;
        }
    }

    float4 o = make_float4(0.f, 0.f, 0.f, 0.f);
#pragma unroll
    for (int h = 0; h < 4; h++) {
        if (den[h] > 0.f) {
            float inv = 0.25f / den[h];
            o.x += acc[h].x * inv; o.y += acc[h].y * inv;
            o.z += acc[h].z * inv; o.w += acc[h].w * inv;
        }
    }
    reinterpret_cast<float4*>(g_gout + (size_t)row * DD)[lane] = o;
}

// ---------------- fp16 mma.sync GEMM, 128x128 block tile ----------------
// C = A[M,K] @ W[Nc,K]^T + bias. 1 MMA/k-step. 8 warps (4m x 2n),
// warp tile 32x64, BK=64, 2-stage cp.async double buffer, 2 CTAs/SM.
// OUT: 0=fp32 Cf; 2=fp16+relu Ch; 3=mixed (cols<1536 fp16 g_qkv stride 1536,
// cols>=1536 fp32 g_skip stride 128 — boundary aligns with 128-col tiles).
#define LDK 72
#define OA   0
#define OW   (128 * LDK * 2)          // 18432
#define STG    (OW + 128 * LDK * 2)   // 36864 per stage
#define SM_TOT (2 * STG)              // 73728 bytes

template<int OUT>
__global__ __launch_bounds__(256, 2) void gemm_fp16(
    const __half* __restrict__ A,
    const __half* __restrict__ W,
    const float* __restrict__ bias,
    float* __restrict__ Cf, __half* __restrict__ Ch,
    int M, int Nc, int K)
{
    extern __shared__ char smem[];
    const uint32_t smb = (uint32_t)__cvta_generic_to_shared(smem);

    const int tid  = threadIdx.x;
    const int lane = tid & 31;
    const int w    = tid >> 5;
    const int wm   = w & 3;       // 4 m-warps, 32 rows each
    const int wn   = w >> 2;      // 2 n-warps, 64 cols each
    const int bm   = blockIdx.y * 128;
    const int bn   = blockIdx.x * 128;

    const int lrow = lane & 7;
    const int quad = lane >> 3;
    const int a_roff = lrow + ((quad & 1) << 3);
    const int a_coff = (quad >> 1) << 3;
    const int b_roff = lrow + ((quad >> 1) << 3);
    const int b_coff = (quad & 1) << 3;

    float acc[2][8][4];
#pragma unroll
    for (int i = 0; i < 2; i++)
#pragma unroll
        for (int j = 0; j < 8; j++)
#pragma unroll
            for (int t = 0; t < 4; t++) acc[i][j][t] = 0.f;

    const int s_row = tid >> 3;       // 0..31
    const int s_c8  = (tid & 7) * 8;  // 8-half (16B) chunks

    auto stage_fn = [&](int s, int k0) {
        uint32_t base = smb + s * STG;
#pragma unroll
        for (int it = 0; it < 4; it++) {
            int row = s_row + it * 32;
            int ga = bm + row; if (ga >= M) ga = M - 1;
            cp16(base + OA + (row * LDK + s_c8) * 2,
                 A + (size_t)ga * K + k0 + s_c8);
            cp16(base + OW + (row * LDK + s_c8) * 2,
                 W + (size_t)(bn + row) * K + k0 + s_c8);
        }
        asm volatile("cp.async.commit_group;");
    };

    const int nCh = K >> 6;
    stage_fn(0, 0);

    for (int c = 0; c < nCh; c++) {
        if (c + 1 < nCh) {
            stage_fn((c + 1) & 1, (c + 1) << 6);
            asm volatile("cp.async.wait_group 1;");
        } else {
            asm volatile("cp.async.wait_group 0;");
        }
        __syncthreads();

        uint32_t base = smb + (c & 1) * STG;
#pragma unroll
        for (int ks = 0; ks < 64; ks += 16) {
            uint32_t af[2][4], bf[8][2];
#pragma unroll
            for (int i = 0; i < 2; i++) {
                uint32_t off = (uint32_t)(((wm * 32 + i * 16 + a_roff) * LDK
                                           + ks + a_coff) * 2);
                ldsm_x4(af[i][0], af[i][1], af[i][2], af[i][3], base + OA + off);
            }
#pragma unroll
            for (int jp = 0; jp < 4; jp++) {
                uint32_t off = (uint32_t)(((wn * 64 + jp * 16 + b_roff) * LDK
                                           + ks + b_coff) * 2);
                ldsm_x4(bf[2 * jp][0], bf[2 * jp][1],
                        bf[2 * jp + 1][0], bf[2 * jp + 1][1],
                        base + OW + off);
            }
#pragma unroll
            for (int i = 0; i < 2; i++)
#pragma unroll
                for (int j = 0; j < 8; j++)
                    mma_f16(acc[i][j], af[i], bf[j]);
        }
        __syncthreads();
    }

    const int qr = lane >> 2;
    const int kq = (lane & 3) * 2;
#pragma unroll
    for (int i = 0; i < 2; i++) {
        int r0 = bm + wm * 32 + i * 16 + qr;
#pragma unroll
        for (int j = 0; j < 8; j++) {
            int c = bn + wn * 64 + j * 8 + kq;
            float b0 = bias[c], b1 = bias[c + 1];
            float v0 = acc[i][j][0] + b0, v1 = acc[i][j][1] + b1;
            float v2 = acc[i][j][2] + b0, v3 = acc[i][j][3] + b1;
            if (OUT == 2) {
                v0 = fmaxf(v0, 0.f); v1 = fmaxf(v1, 0.f);
                v2 = fmaxf(v2, 0.f); v3 = fmaxf(v3, 0.f);
            }
#pragma unroll
            for (int hrow = 0; hrow < 2; hrow++) {
                int r = r0 + hrow * 8;
                if (r >= M) continue;
                float va = hrow ? v2 : v0;
                float vb = hrow ? v3 : v1;
                if (OUT == 0) {
                    *reinterpret_cast<float2*>(Cf + (size_t)r * Nc + c) =
                        make_float2(va, vb);
                } else if (OUT == 2) {
                    *reinterpret_cast<__half2*>(Ch + (size_t)r * Nc + c) =
                        __floats2half2_rn(va, vb);
                } else { // OUT == 3
                    if (c < 1536)
                        *reinterpret_cast<__half2*>(Ch + (size_t)r * 1536 + c) =
                            __floats2half2_rn(va, vb);
                    else
                        *reinterpret_cast<float2*>(Cf + (size_t)r * DD + (c - 1536)) =
                            make_float2(va, vb);
                }
            }
        }
    }
}

// ---------------- layernorm ----------------
__device__ __forceinline__ float4 ln_core(float4 vv, int lane,
                                          const float* __restrict__ g,
                                          const float* __restrict__ b) {
    float sum = vv.x + vv.y + vv.z + vv.w;
    float sq = vv.x * vv.x + vv.y * vv.y + vv.z * vv.z + vv.w * vv.w;
#pragma unroll
    for (int o = 16; o > 0; o >>= 1) {
        sum += __shfl_xor_sync(0xffffffffu, sum, o);
        sq  += __shfl_xor_sync(0xffffffffu, sq, o);
    }
    float mu = sum * (1.f / 128.f);
    float var = sq * (1.f / 128.f) - mu * mu;
    float rstd = rsqrtf(var + 1e-5f);
    float4 gv = reinterpret_cast<const float4*>(g)[lane];
    float4 bv = reinterpret_cast<const float4*>(b)[lane];
    float4 o;
    o.x = (vv.x - mu) * rstd * gv.x + bv.x;
    o.y = (vv.y - mu) * rstd * gv.y + bv.y;
    o.z = (vv.z - mu) * rstd * gv.z + bv.z;
    o.w = (vv.w - mu) * rstd * gv.w + bv.w;
    return o;
}

// x2 = LN2(LN1(x + gout + skip) + tout); emits x2 fp32 + fp16
__global__ void ln12_kernel(const float* __restrict__ x,
                            const float* __restrict__ ln1g, const float* __restrict__ ln1b,
                            const float* __restrict__ ln2g, const float* __restrict__ ln2b) {
    int row = (blockIdx.x * blockDim.x + threadIdx.x) >> 5;
    int lane = threadIdx.x & 31;
    if (row >= NN) return;
    float4 xv = reinterpret_cast<const float4*>(x + (size_t)row * DD)[lane];
    float4 sv = reinterpret_cast<const float4*>(g_skip + (size_t)row * DD)[lane];
    float4 gv = reinterpret_cast<const float4*>(g_gout + (size_t)row * DD)[lane];
    float4 vv = make_float4(xv.x + sv.x + gv.x, xv.y + sv.y + gv.y,
                            xv.z + sv.z + gv.z, xv.w + sv.w + gv.w);
    float4 o1 = ln_core(vv, lane, ln1g, ln1b);
    float4 tv = reinterpret_cast<const float4*>(g_tout + (size_t)row * DD)[lane];
    float4 v2 = make_float4(o1.x + tv.x, o1.y + tv.y, o1.z + tv.z, o1.w + tv.w);
    float4 o2 = ln_core(v2, lane, ln2g, ln2b);
    reinterpret_cast<float4*>(g_x2 + (size_t)row * DD)[lane] = o2;
    size_t base = (size_t)row * DD + lane * 4;
    *reinterpret_cast<__half2*>(g_x2f + base)     = __floats2half2_rn(o2.x, o2.y);
    *reinterpret_cast<__half2*>(g_x2f + base + 2) = __floats2half2_rn(o2.z, o2.w);
}

// out = LN(a + b)
__global__ void ln_add_kernel(const float* __restrict__ a, const float* __restrict__ bb,
                              const float* __restrict__ g, const float* __restrict__ beta,
                              float* __restrict__ out) {
    int row = (blockIdx.x * blockDim.x + threadIdx.x) >> 5;
    int lane = threadIdx.x & 31;
    if (row >= NN) return;
    float4 av = reinterpret_cast<const float4*>(a + (size_t)row * DD)[lane];
    float4 bv = reinterpret_cast<const float4*>(bb + (size_t)row * DD)[lane];
    float4 vv = make_float4(av.x + bv.x, av.y + bv.y, av.z + bv.z, av.w + bv.w);
    float4 o = ln_core(vv, lane, g, beta);
    reinterpret_cast<float4*>(out + (size_t)row * DD)[lane] = o;
}

// ---------------- launch ----------------
static void* sym(const void* s) { void* p = nullptr; cudaGetSymbolAddress(&p, s); return p; }

extern "C" void kernel_launch(void* const* d_in, const int* in_sizes, int n_in,
                              void* d_out, int out_size)
{
    const float* x    = (const float*)d_in[0];
    const float* te   = (const float*)d_in[1];
    const float* gq_w = (const float*)d_in[2];  const float* gq_b = (const float*)d_in[3];
    const float* gk_w = (const float*)d_in[4];  const float* gk_b = (const float*)d_in[5];
    const float* gv_w = (const float*)d_in[6];  const float* gv_b = (const float*)d_in[7];
    const float* gs_w = (const float*)d_in[8];  const float* gs_b = (const float*)d_in[9];
    // mha_wq/bq, mha_wk/bk dead: softmax over one kv position is exactly 1.
    const float* wv   = (const float*)d_in[14]; const float* bv   = (const float*)d_in[15];
    const float* wo   = (const float*)d_in[16]; const float* bo   = (const float*)d_in[17];
    const float* w1   = (const float*)d_in[18]; const float* b1   = (const float*)d_in[19];
    const float* w2   = (const float*)d_in[20]; const float* b2   = (const float*)d_in[21];
    const float* ln1g = (const float*)d_in[22]; const float* ln1b = (const float*)d_in[23];
    const float* ln2g = (const float*)d_in[24]; const float* ln2b = (const float*)d_in[25];
    const float* ln3g = (const float*)d_in[26]; const float* ln3b = (const float*)d_in[27];
    const int*   ei   = (const int*)d_in[28];
    float* out = (float*)d_out;

    float* skip_p = (float*)sym(g_skip);
    float* tout_p = (float*)sym(g_tout);
    float* x2_p   = (float*)sym(g_x2);
    float* ffn_p  = (float*)sym(g_ffn);
    float* bf_p   = (float*)sym(g_bias_f);
    float* wc_p   = (float*)sym(g_wc);
    float* bc_p   = (float*)sym(g_bc);

    __half* qkv_p = (__half*)sym(g_qkv);
    __half* xf   = (__half*)sym(g_xf);
    __half* tef  = (__half*)sym(g_tef);
    __half* x2f  = (__half*)sym(g_x2f);
    __half* hf   = (__half*)sym(g_hf);
    __half* wf   = (__half*)sym(g_wf);
    __half* wcf  = (__half*)sym(g_wcf);
    __half* w1f  = (__half*)sym(g_w1f);
    __half* w2f  = (__half*)sym(g_w2f);

    cudaFuncSetAttribute(gemm_fp16<0>, cudaFuncAttributeMaxDynamicSharedMemorySize, SM_TOT);
    cudaFuncSetAttribute(gemm_fp16<2>, cudaFuncAttributeMaxDynamicSharedMemorySize, SM_TOT);
    cudaFuncSetAttribute(gemm_fp16<3>, cudaFuncAttributeMaxDynamicSharedMemorySize, SM_TOT);

    const int MB = (NN + 127) / 128;       // 157
    const int NSCAN = (NN + 1023) / 1024;  // 20

    setup_kernel<<<(NN + 255) / 256, 256>>>(gq_b, gk_b, gv_b, gs_b);
    compose_temporal<<<128, 128>>>(wo, wv, bv, bo);

    // CSR build
    hist_kernel<<<(EE + 255) / 256, 256>>>(ei);
    scanA_kernel<<<NSCAN, 1024>>>();
    scanC_kernel<<<(NN + 255) / 256, 256>>>();
    fill_kernel<<<(EE + 255) / 256, 256>>>(ei);

    AJs jobs;
    jobs.j[0] = {x,    xf,  NN * DD / 4};
    jobs.j[1] = {te,   tef, NN * DD / 4};
    jobs.j[2] = {gq_w, wf,              512 * 128 / 4};
    jobs.j[3] = {gk_w, wf + 512 * 128,  512 * 128 / 4};
    jobs.j[4] = {gv_w, wf + 1024 * 128, 512 * 128 / 4};
    jobs.j[5] = {gs_w, wf + 1536 * 128, 128 * 128 / 4};
    jobs.j[6] = {wc_p, wcf, 128 * 128 / 4};
    jobs.j[7] = {w1,   w1f, 512 * 128 / 4};
    jobs.j[8] = {w2,   w2f, 128 * 512 / 4};
    conv_a<<<dim3(64, 9), 256>>>(jobs);

    // fused q|k|v|skip projection: mixed output (q,k,v fp16; skip fp32)
    gemm_fp16<3><<<dim3(NFUSE / 128, MB), 256, SM_TOT>>>(
        xf, wf, bf_p, skip_p, qkv_p, NN, NFUSE, 128);
    // temporal (composed): tout = te @ Wc^T + bc
    gemm_fp16<0><<<dim3(1, MB), 256, SM_TOT>>>(
        tef, wcf, bc_p, tout_p, nullptr, NN, 128, 128);

    // graph attention
    edge_dst_kernel<<<(NN + 7) / 8, 256>>>();

    // x2 = LN2(LN1(x+gout+skip) + tout)
    ln12_kernel<<<(NN + 7) / 8, 256>>>(x, ln1g, ln1b, ln2g, ln2b);
    // FFN
    gemm_fp16<2><<<dim3(4, MB), 256, SM_TOT>>>(
        x2f, w1f, b1, nullptr, hf, NN, 512, 128);
    gemm_fp16<0><<<dim3(1, MB), 256, SM_TOT>>>(
        hf, w2f, b2, ffn_p, nullptr, NN, 128, 512);
    ln_add_kernel<<<(NN + 7) / 8, 256>>>(x2_p, ffn_p, ln3g, ln3b, out);
}